// round 11
// baseline (speedup 1.0000x reference)
#include <cuda_runtime.h>
#include <cuda_fp16.h>
#include <cstdint>

// Problem constants (fixed by setup_inputs)
#define SEQ  8192
#define DKD  128
#define DVD  128
#define BT   64
#define NCH  128          // SEQ/BT
#define BHT  16           // BB*HHD
#define NCHUNKS 2048      // BHT*NCH
#define OSZ  16777216     // BHT*SEQ*DVD  (size of o)

// ---- fp16 helpers ----
__device__ __forceinline__ uint32_t h2(float lo, float hi) {
    __half2 h = __floats2half2_rn(lo, hi);
    return *reinterpret_cast<uint32_t*>(&h);
}
__device__ __forceinline__ void mma16(float& d0, float& d1, float& d2, float& d3,
    uint32_t a0, uint32_t a1, uint32_t a2, uint32_t a3, uint32_t b0, uint32_t b1) {
    asm("mma.sync.aligned.m16n8k16.row.col.f32.f16.f16.f32 "
        "{%0,%1,%2,%3},{%4,%5,%6,%7},{%8,%9},{%0,%1,%2,%3};"
        : "+f"(d0), "+f"(d1), "+f"(d2), "+f"(d3)
        : "r"(a0), "r"(a1), "r"(a2), "r"(a3), "r"(b0), "r"(b1));
}

// Scratch (device globals; fp16 fragment-major, half2 packed along K)
__device__ uint32_t g_wfh [NCHUNKS*4096];  // -w   64x128: block b = mr*8 + kc(8)
__device__ uint32_t g_qefh[NCHUNKS*4096];  // qe   64x128: same blocks
__device__ uint32_t g_krfh[NCHUNKS*4096];  // krT 128x64 : block b = cr*4 + kc(4)
__device__ uint32_t g_Afh [NCHUNKS*2048];  // Aqk  64x64 : block b = mr*4 + kc(4)
__device__ __half   g_uh  [BHT*SEQ*DVD];   // u fp16 [row][V]
__device__ float    g_egl [NCHUNKS];

#define P1_SMEM ((8704*2 + 4352 + 3*64)*4)

// ---------------------------------------------------------------------------
// Phase 1: per-chunk (2048 CTAs). Both 64x64 gram matmuls (A0, Aqk) on fp16
// mma; A0 scaled+stored fp32 to smem for the (fp32) triangular solve.
// (UNCHANGED from round 10 — passed at ~175us.)
// ---------------------------------------------------------------------------
__global__ void __launch_bounds__(256, 2) p1_kernel(
    const float* __restrict__ q, const float* __restrict__ k,
    const float* __restrict__ v, const float* __restrict__ g,
    const float* __restrict__ beta)
{
    extern __shared__ float sm[];
    float* skT = sm;                 // [128][68] k transposed (normalized)
    float* sqT = skT + 8704;         // [128][68] q transposed; later: -w staged
    float* sA0 = sqT + 8704;         // [64][68]  strictly-lower A0 (fp32)
    float* seg = sA0 + 4352;         // [64] exp(cumsum g)
    float* sie = seg + 64;           // [64] 1/seg
    float* sb  = sie + 64;           // [64] beta
    __shared__ float sgr[BT];

    const int cid = blockIdx.x;
    const int bh  = cid / NCH, n = cid % NCH;
    const int rowbase = bh*SEQ + n*BT;
    const int t = threadIdx.x;
    const int lane = t & 31, wid = t >> 5;
    const int gq = lane >> 2, tig = lane & 3;

    if (t < BT) { sb[t] = beta[rowbase + t]; sgr[t] = g[rowbase + t]; }
    __syncthreads();
    if (t < 32) {
        float a = sgr[2*t], b = sgr[2*t+1];
        float s = a + b;
        #pragma unroll
        for (int o = 1; o < 32; o <<= 1) {
            float y = __shfl_up_sync(0xffffffffu, s, o);
            if (t >= o) s += y;
        }
        float gc1 = s, gc0 = s - b;
        seg[2*t  ] = __expf(gc0);  sie[2*t  ] = __expf(-gc0);
        seg[2*t+1] = __expf(gc1);  sie[2*t+1] = __expf(-gc1);
        if (t == 31) g_egl[cid] = seg[63];
    }
    // normalize rows of q,k; store transposed
    for (int r = wid; r < BT; r += 8) {
        const float* kp = k + (size_t)(rowbase + r)*DKD;
        const float* qp = q + (size_t)(rowbase + r)*DKD;
        float k0=kp[lane],k1=kp[lane+32],k2=kp[lane+64],k3=kp[lane+96];
        float q0=qp[lane],q1=qp[lane+32],q2=qp[lane+64],q3=qp[lane+96];
        float ssk = k0*k0+k1*k1+k2*k2+k3*k3;
        float ssq = q0*q0+q1*q1+q2*q2+q3*q3;
        #pragma unroll
        for (int o = 16; o; o >>= 1) {
            ssk += __shfl_xor_sync(0xffffffffu, ssk, o);
            ssq += __shfl_xor_sync(0xffffffffu, ssq, o);
        }
        float ik = 1.f/(sqrtf(ssk)+1e-6f);
        float iq = 0.08838834764831845f/(sqrtf(ssq)+1e-6f);  // K^-0.5 folded in
        skT[(lane    )*68+r]=k0*ik; skT[(lane+32)*68+r]=k1*ik;
        skT[(lane+64)*68+r]=k2*ik; skT[(lane+96)*68+r]=k3*ik;
        sqT[(lane    )*68+r]=q0*iq; sqT[(lane+32)*68+r]=q1*iq;
        sqT[(lane+64)*68+r]=q2*iq; sqT[(lane+96)*68+r]=q3*iq;
    }
    __syncthreads();

    // ---- warps 0-3: Aqk = q·k^T via mma -> g_Afh; then qef emit
    //      warps 4-7: A0  = k·k^T via mma -> sA0 (fp32, lower tri); then krf
    if (wid < 4) {
        const int mr = wid;
        const int i0 = 16*mr + gq, i8 = i0 + 8;
        float D[8][4];
        #pragma unroll
        for (int z = 0; z < 8; z++) { D[z][0]=0.f; D[z][1]=0.f; D[z][2]=0.f; D[z][3]=0.f; }
        #pragma unroll
        for (int kc = 0; kc < 8; kc++) {
            int kb = 16*kc;
            uint32_t a0 = h2(sqT[(kb+2*tig  )*68+i0], sqT[(kb+2*tig+1)*68+i0]);
            uint32_t a1 = h2(sqT[(kb+2*tig  )*68+i8], sqT[(kb+2*tig+1)*68+i8]);
            uint32_t a2 = h2(sqT[(kb+2*tig+8)*68+i0], sqT[(kb+2*tig+9)*68+i0]);
            uint32_t a3 = h2(sqT[(kb+2*tig+8)*68+i8], sqT[(kb+2*tig+9)*68+i8]);
            #pragma unroll
            for (int nt = 0; nt < 8; nt++) {
                int jn = 8*nt + gq;
                uint32_t b0 = h2(skT[(kb+2*tig  )*68+jn], skT[(kb+2*tig+1)*68+jn]);
                uint32_t b1 = h2(skT[(kb+2*tig+8)*68+jn], skT[(kb+2*tig+9)*68+jn]);
                mma16(D[nt][0],D[nt][1],D[nt][2],D[nt][3], a0,a1,a2,a3, b0,b1);
            }
        }
        float s_i0 = seg[i0], s_i8 = seg[i8];
        #pragma unroll
        for (int c = 0; c < 4; c++) {
            int j0 = 16*c + 2*tig;
            float f00 = (j0   < i0) ? s_i0*sie[j0  ] : ((j0  ==i0)?1.f:0.f);
            float f01 = (j0+1 < i0) ? s_i0*sie[j0+1] : ((j0+1==i0)?1.f:0.f);
            float f80 = (j0   < i8) ? s_i8*sie[j0  ] : ((j0  ==i8)?1.f:0.f);
            float f81 = (j0+1 < i8) ? s_i8*sie[j0+1] : ((j0+1==i8)?1.f:0.f);
            float h00 = (j0+8 < i0) ? s_i0*sie[j0+8] : ((j0+8==i0)?1.f:0.f);
            float h01 = (j0+9 < i0) ? s_i0*sie[j0+9] : ((j0+9==i0)?1.f:0.f);
            float h80 = (j0+8 < i8) ? s_i8*sie[j0+8] : ((j0+8==i8)?1.f:0.f);
            float h81 = (j0+9 < i8) ? s_i8*sie[j0+9] : ((j0+9==i8)?1.f:0.f);
            uint4 o;
            o.x = h2(D[2*c  ][0]*f00, D[2*c  ][1]*f01);
            o.y = h2(D[2*c  ][2]*f80, D[2*c  ][3]*f81);
            o.z = h2(D[2*c+1][0]*h00, D[2*c+1][1]*h01);
            o.w = h2(D[2*c+1][2]*h80, D[2*c+1][3]*h81);
            *(uint4*)&g_Afh[(size_t)cid*2048 + (mr*4+c)*128 + lane*4] = o;
        }
        // qef emit
        for (int task = t; task < 1024; task += 128) {
            int b = task >> 5, l = task & 31;
            int ii = 16*(b>>3) + (l>>2), k0 = 16*(b&7) + (l&3)*2;
            float s0 = seg[ii], s1 = seg[ii+8];
            uint4 o;
            o.x = h2(sqT[(k0  )*68+ii  ]*s0, sqT[(k0+1)*68+ii  ]*s0);
            o.y = h2(sqT[(k0  )*68+ii+8]*s1, sqT[(k0+1)*68+ii+8]*s1);
            o.z = h2(sqT[(k0+8)*68+ii  ]*s0, sqT[(k0+9)*68+ii  ]*s0);
            o.w = h2(sqT[(k0+8)*68+ii+8]*s1, sqT[(k0+9)*68+ii+8]*s1);
            *(uint4*)&g_qefh[(size_t)cid*4096 + b*128 + l*4] = o;
        }
    } else {
        const int mr = wid - 4;
        const int i0 = 16*mr + gq, i8 = i0 + 8;
        float D[8][4];
        #pragma unroll
        for (int z = 0; z < 8; z++) { D[z][0]=0.f; D[z][1]=0.f; D[z][2]=0.f; D[z][3]=0.f; }
        #pragma unroll
        for (int kc = 0; kc < 8; kc++) {
            int kb = 16*kc;
            uint32_t a0 = h2(skT[(kb+2*tig  )*68+i0], skT[(kb+2*tig+1)*68+i0]);
            uint32_t a1 = h2(skT[(kb+2*tig  )*68+i8], skT[(kb+2*tig+1)*68+i8]);
            uint32_t a2 = h2(skT[(kb+2*tig+8)*68+i0], skT[(kb+2*tig+9)*68+i0]);
            uint32_t a3 = h2(skT[(kb+2*tig+8)*68+i8], skT[(kb+2*tig+9)*68+i8]);
            #pragma unroll
            for (int nt = 0; nt < 8; nt++) {
                int jn = 8*nt + gq;
                uint32_t b0 = h2(skT[(kb+2*tig  )*68+jn], skT[(kb+2*tig+1)*68+jn]);
                uint32_t b1 = h2(skT[(kb+2*tig+8)*68+jn], skT[(kb+2*tig+9)*68+jn]);
                mma16(D[nt][0],D[nt][1],D[nt][2],D[nt][3], a0,a1,a2,a3, b0,b1);
            }
        }
        // scale + store strict lower triangle (fp32)
        float bs0 = seg[i0]*sb[i0], bs8 = seg[i8]*sb[i8];
        #pragma unroll
        for (int nt = 0; nt < 8; nt++) {
            int j0 = 8*nt + 2*tig;
            if (j0   < i0) sA0[i0*68+j0  ] = D[nt][0]*bs0*sie[j0  ];
            if (j0+1 < i0) sA0[i0*68+j0+1] = D[nt][1]*bs0*sie[j0+1];
            if (j0   < i8) sA0[i8*68+j0  ] = D[nt][2]*bs8*sie[j0  ];
            if (j0+1 < i8) sA0[i8*68+j0+1] = D[nt][3]*bs8*sie[j0+1];
        }
        // krf emit
        float egl2 = seg[BT-1];
        for (int task = t - 128; task < 1024; task += 128) {
            int b = task >> 5, l = task & 31;
            int c0 = 16*(b>>2) + (l>>2), ii = 16*(b&3) + (l&3)*2;
            float e0 = egl2*sie[ii], e1 = egl2*sie[ii+1];
            float e8 = egl2*sie[ii+8], e9 = egl2*sie[ii+9];
            uint4 o;
            o.x = h2(skT[(c0  )*68+ii  ]*e0, skT[(c0  )*68+ii+1]*e1);
            o.y = h2(skT[(c0+8)*68+ii  ]*e0, skT[(c0+8)*68+ii+1]*e1);
            o.z = h2(skT[(c0  )*68+ii+8]*e8, skT[(c0  )*68+ii+9]*e9);
            o.w = h2(skT[(c0+8)*68+ii+8]*e8, skT[(c0+8)*68+ii+9]*e9);
            *(uint4*)&g_krfh[(size_t)cid*4096 + b*128 + l*4] = o;
        }
    }
    __syncthreads();   // sA0 ready; emits done before sqT is overwritten

    // Unit-lower triangular solve (fp32)
    {
        float x[64];
        if (t < 128) {
            #pragma unroll
            for (int i = 0; i < 64; i++) x[i] = sb[i]*skT[t*68+i]*seg[i];
        } else {
            const float* vp = v + (size_t)rowbase*DVD + (t - 128);
            #pragma unroll
            for (int i = 0; i < 64; i++) x[i] = sb[i]*vp[i*DVD];
        }
        #pragma unroll
        for (int i = 1; i < 64; i++) {
            float s0 = 0.f, s1 = 0.f, s2 = 0.f, s3 = 0.f;
            int j = 0;
            #pragma unroll
            for (; j + 4 <= i; j += 4) {
                float4 a4 = *(const float4*)&sA0[i*68+j];
                s0 += a4.x*x[j]; s1 += a4.y*x[j+1];
                s2 += a4.z*x[j+2]; s3 += a4.w*x[j+3];
            }
            #pragma unroll
            for (; j < i; j++) s0 += sA0[i*68+j]*x[j];
            x[i] -= (s0 + s1) + (s2 + s3);
        }
        if (t < 128) {
            #pragma unroll
            for (int i = 0; i < 64; i++) sqT[t*68+i] = -x[i];   // stage NEGATED w
        } else {
            #pragma unroll
            for (int i = 0; i < 64; i++)
                g_uh[(size_t)(rowbase+i)*DVD + (t-128)] = __float2half_rn(x[i]);
        }
    }
    __syncthreads();

    // -w fragment emit (all 256 threads)
    for (int task = t; task < 1024; task += 256) {
        int b = task >> 5, l = task & 31;
        int i0 = 16*(b>>3) + (l>>2), k0 = 16*(b&7) + (l&3)*2;
        uint4 o;
        o.x = h2(sqT[(k0  )*68+i0  ], sqT[(k0+1)*68+i0  ]);
        o.y = h2(sqT[(k0  )*68+i0+8], sqT[(k0+1)*68+i0+8]);
        o.z = h2(sqT[(k0+8)*68+i0  ], sqT[(k0+9)*68+i0  ]);
        o.w = h2(sqT[(k0+8)*68+i0+8], sqT[(k0+9)*68+i0+8]);
        *(uint4*)&g_wfh[(size_t)cid*4096 + b*128 + l*4] = o;
    }
}

// ---------------------------------------------------------------------------
// Phase 2: fp16 mma recurrence, R8 pipeline, now 256 CTAs (16 bh x 16 V-slices
// of width 8) at occupancy 2 — co-resident independent CTAs hide stalls.
//   v-warps 0-3: L1 v=u+(-w)@S -> L3 S update (32-row strip each)
//   o-warps 4-7: qe@S + one-step-delayed Aqk@v_new
// ---------------------------------------------------------------------------
__global__ void __launch_bounds__(256, 2) p2_kernel(float* __restrict__ out, int write_sf)
{
    __shared__ uint32_t sSb [2][8*68];    // S mirror [n][row-pair pad68], dbl buf
    __shared__ uint32_t svnb[2][8*36];    // v_new    [n][row-pair pad36], dbl buf
    __shared__ float    segl[NCH];

    const int t = threadIdx.x;
    const int w = t >> 5, l = t & 31, g = l >> 2, tig = l & 3;
    const bool isv = (w < 4);
    const int mr = w & 3;
    const int bh = blockIdx.x >> 4;
    const int vb = (blockIdx.x & 15) * 8;

    for (int i = t; i < 8*68; i += 256) sSb[0][i] = 0u;
    if (t < NCH) segl[t] = g_egl[bh*NCH + t];
    __syncthreads();

    float S[8];                        // v-warps: fp32 state strip (32 rows x 8 cols)
    #pragma unroll
    for (int i = 0; i < 8; i++) S[i] = 0.f;
    float C[4];                        // o-warps: carried o accumulator
    uint4 AF[4];                       // o-warps: carried Aqk frags (prev step)
    uint4 A[8];                        // L1 A frags (prefetched)
    uint4 K[8];                        // v-warps: krT frags (prefetched)
    uint32_t ur[2];                    // v-warps: u half2 regs (prefetched)

    const uint32_t* aL1 = isv ? g_wfh : g_qefh;
    {
        const uint4* Ab = (const uint4*)(aL1 + (size_t)(bh*NCH)*4096) + (mr*8)*32 + l;
        #pragma unroll
        for (int j = 0; j < 8; j++) A[j] = Ab[j*32];
        if (isv) {
            const uint4* Kb = (const uint4*)(g_krfh + (size_t)(bh*NCH)*4096) + l;
            #pragma unroll
            for (int mt = 0; mt < 2; mt++)
                #pragma unroll
                for (int kc = 0; kc < 4; kc++)
                    K[mt*4+kc] = Kb[((2*mr+mt)*4 + kc)*32];
            const uint32_t* up = (const uint32_t*)(g_uh + (size_t)(bh*SEQ + 16*mr + g)*DVD + vb);
            ur[0] = up[tig]; ur[1] = up[512+tig];
        }
    }

    for (int n = 0; n < NCH; n++) {
        const int cid = bh*NCH + n;
        const size_t rb = (size_t)bh*SEQ + (size_t)n*BT;
        const int cur = n & 1;
        uint32_t* sSr  = sSb[cur];
        uint32_t* sSw  = sSb[cur^1];
        uint32_t* svnw = svnb[cur];
        uint32_t* svno = svnb[cur^1];

        if (isv) {
            // ---- L1: v = u + (-w)@S over K=128
            float2 f0 = __half22float2(*(__half2*)&ur[0]);
            float2 f1 = __half22float2(*(__half2*)&ur[1]);
            float a0=f0.x, a1=f0.y, a2=f1.x, a3=f1.y;
            #pragma unroll
            for (int kc = 0; kc < 8; kc++) {
                uint32_t b00 = sSr[g*68 + 8*kc     + tig];
                uint32_t b01 = sSr[g*68 + 8*kc + 4 + tig];
                mma16(a0,a1,a2,a3, A[kc].x,A[kc].y,A[kc].z,A[kc].w, b00,b01);
            }
            if (n + 1 < NCH) {   // prefetch next -w frags
                const uint4* Ab = (const uint4*)(g_wfh + (size_t)(cid+1)*4096) + (mr*8)*32 + l;
                #pragma unroll
                for (int j = 0; j < 8; j++) A[j] = Ab[j*32];
            }
            // publish v_new (4 halves): rows 16mr+g, +8; cols 2tig, 2tig+1
            {
                __half* svnh = (__half*)svnw;
                int p0 = (16*mr + g) >> 1, hb = g & 1;
                svnh[((2*tig  )*36 + p0  )*2 + hb] = __float2half_rn(a0);
                svnh[((2*tig+1)*36 + p0  )*2 + hb] = __float2half_rn(a1);
                svnh[((2*tig  )*36 + p0+4)*2 + hb] = __float2half_rn(a2);
                svnh[((2*tig+1)*36 + p0+4)*2 + hb] = __float2half_rn(a3);
            }
            asm volatile("bar.sync 1, 128;" ::: "memory");   // v-warps only

            // ---- L3: S = egl*S + krT @ v_new (2 m-tiles, K=64)
            {
                const float egl = segl[n];
                #pragma unroll
                for (int i = 0; i < 8; i++) S[i] *= egl;
                #pragma unroll
                for (int kc = 0; kc < 4; kc++) {
                    uint32_t b00 = svnw[g*36 + 8*kc     + tig];
                    uint32_t b01 = svnw[g*36 + 8*kc + 4 + tig];
                    mma16(S[0],S[1],S[2],S[3], K[kc  ].x,K[kc  ].y,K[kc  ].z,K[kc  ].w, b00,b01);
                    mma16(S[4],S[5],S[6],S[7], K[4+kc].x,K[4+kc].y,K[4+kc].z,K[4+kc].w, b00,b01);
                }
                __half* sSh = (__half*)sSw;
                #pragma unroll
                for (int mt = 0; mt < 2; mt++) {
                    int r = 32*mr + 16*mt + g;
                    int p = r >> 1, hb2 = r & 1;
                    const float* sp = S + mt*4;
                    sSh[((2*tig  )*68 + p  )*2 + hb2] = __float2half_rn(sp[0]);
                    sSh[((2*tig+1)*68 + p  )*2 + hb2] = __float2half_rn(sp[1]);
                    sSh[((2*tig  )*68 + p+4)*2 + hb2] = __float2half_rn(sp[2]);
                    sSh[((2*tig+1)*68 + p+4)*2 + hb2] = __float2half_rn(sp[3]);
                }
            }
            if (n + 1 < NCH) {   // prefetch next K, u
                const uint4* Kb = (const uint4*)(g_krfh + (size_t)(cid+1)*4096) + l;
                #pragma unroll
                for (int mt = 0; mt < 2; mt++)
                    #pragma unroll
                    for (int kc = 0; kc < 4; kc++)
                        K[mt*4+kc] = Kb[((2*mr+mt)*4 + kc)*32];
                const uint32_t* up = (const uint32_t*)(g_uh + (rb + BT + 16*mr + g)*DVD + vb);
                ur[0] = up[tig]; ur[1] = up[512+tig];
            }
        } else {
            // ---- finish o(n-1): C += Aqk(n-1) @ v_new(n-1); store
            if (n > 0) {
                #pragma unroll
                for (int kc = 0; kc < 4; kc++) {
                    uint32_t b00 = svno[g*36 + 8*kc     + tig];
                    uint32_t b01 = svno[g*36 + 8*kc + 4 + tig];
                    mma16(C[0],C[1],C[2],C[3], AF[kc].x,AF[kc].y,AF[kc].z,AF[kc].w, b00,b01);
                }
                float* d0 = out + (rb - BT + 16*mr + g)*DVD + vb;
                *(float2*)(d0 +         2*tig) = make_float2(C[0], C[1]);
                *(float2*)(d0 + 8*DVD + 2*tig) = make_float2(C[2], C[3]);
            }
            // load this step's Aqk frags (used next step)
            {
                const uint4* Fb = (const uint4*)(g_Afh + (size_t)cid*2048) + (mr*4)*32 + l;
                #pragma unroll
                for (int kc = 0; kc < 4; kc++) AF[kc] = Fb[kc*32];
            }
            // ---- qe(n) @ S(n) into fresh C
            C[0]=0.f; C[1]=0.f; C[2]=0.f; C[3]=0.f;
            #pragma unroll
            for (int kc = 0; kc < 8; kc++) {
                uint32_t b00 = sSr[g*68 + 8*kc     + tig];
                uint32_t b01 = sSr[g*68 + 8*kc + 4 + tig];
                mma16(C[0],C[1],C[2],C[3], A[kc].x,A[kc].y,A[kc].z,A[kc].w, b00,b01);
            }
            if (n + 1 < NCH) {   // prefetch next qe frags
                const uint4* Ab = (const uint4*)(g_qefh + (size_t)(cid+1)*4096) + (mr*8)*32 + l;
                #pragma unroll
                for (int j = 0; j < 8; j++) A[j] = Ab[j*32];
            }
        }
        __syncthreads();   // publishes sS[cur^1] + svn[cur]; retires svn[cur^1]
    }

    // o epilogue: finish the last chunk
    if (!isv) {
        uint32_t* svno = svnb[(NCH-1) & 1];
        #pragma unroll
        for (int kc = 0; kc < 4; kc++) {
            uint32_t b00 = svno[g*36 + 8*kc     + tig];
            uint32_t b01 = svno[g*36 + 8*kc + 4 + tig];
            mma16(C[0],C[1],C[2],C[3], AF[kc].x,AF[kc].y,AF[kc].z,AF[kc].w, b00,b01);
        }
        float* d0 = out + ((size_t)bh*SEQ + (size_t)(NCH-1)*BT + 16*mr + g)*DVD + vb;
        *(float2*)(d0 +         2*tig) = make_float2(C[0], C[1]);
        *(float2*)(d0 + 8*DVD + 2*tig) = make_float2(C[2], C[3]);
    }

    if (write_sf && isv) {
        float* base = out + OSZ + (size_t)bh*DKD*DVD + vb;
        #pragma unroll
        for (int mt = 0; mt < 2; mt++) {
            int r = 32*mr + 16*mt + g;
            const float* sp = S + mt*4;
            *(float2*)(base + (size_t)(r    )*DVD + 2*tig) = make_float2(sp[0], sp[1]);
            *(float2*)(base + (size_t)(r + 8)*DVD + 2*tig) = make_float2(sp[2], sp[3]);
        }
    }
}

// ---------------------------------------------------------------------------
extern "C" void kernel_launch(void* const* d_in, const int* in_sizes, int n_in,
                              void* d_out, int out_size)
{
    const float* q    = (const float*)d_in[0];
    const float* k    = (const float*)d_in[1];
    const float* v    = (const float*)d_in[2];
    const float* g    = (const float*)d_in[3];
    const float* beta = (const float*)d_in[4];
    float* out = (float*)d_out;

    cudaFuncSetAttribute(p1_kernel, cudaFuncAttributeMaxDynamicSharedMemorySize, P1_SMEM);

    p1_kernel<<<NCHUNKS, 256, P1_SMEM>>>(q, k, v, g, beta);

    int wsf = (out_size > OSZ) ? 1 : 0;
    p2_kernel<<<BHT*16, 256>>>(out, wsf);
}

// round 12
// speedup vs baseline: 1.0765x; 1.0765x over previous
#include <cuda_runtime.h>
#include <cuda_fp16.h>
#include <cstdint>

// Problem constants (fixed by setup_inputs)
#define SEQ  8192
#define DKD  128
#define DVD  128
#define BT   64
#define NCH  128          // SEQ/BT
#define BHT  16           // BB*HHD
#define NCHUNKS 2048      // BHT*NCH
#define OSZ  16777216     // BHT*SEQ*DVD  (size of o)

typedef unsigned long long u64;

// ---- fp16 helpers ----
__device__ __forceinline__ uint32_t h2(float lo, float hi) {
    __half2 h = __floats2half2_rn(lo, hi);
    return *reinterpret_cast<uint32_t*>(&h);
}
__device__ __forceinline__ void mma16(float& d0, float& d1, float& d2, float& d3,
    uint32_t a0, uint32_t a1, uint32_t a2, uint32_t a3, uint32_t b0, uint32_t b1) {
    asm("mma.sync.aligned.m16n8k16.row.col.f32.f16.f16.f32 "
        "{%0,%1,%2,%3},{%4,%5,%6,%7},{%8,%9},{%0,%1,%2,%3};"
        : "+f"(d0), "+f"(d1), "+f"(d2), "+f"(d3)
        : "r"(a0), "r"(a1), "r"(a2), "r"(a3), "r"(b0), "r"(b1));
}

// ---- packed f32x2 helpers (exact fp32 lanes) ----
__device__ __forceinline__ u64 pkab(float a, float b) {
    u64 r; asm("mov.b64 %0,{%1,%2};" : "=l"(r) : "f"(a), "f"(b)); return r;
}
__device__ __forceinline__ u64 fma2(u64 a, u64 b, u64 c) {
    u64 d; asm("fma.rn.f32x2 %0,%1,%2,%3;" : "=l"(d) : "l"(a), "l"(b), "l"(c)); return d;
}
__device__ __forceinline__ float2 up2(u64 a) {
    float2 f; asm("mov.b64 {%0,%1},%2;" : "=f"(f.x), "=f"(f.y) : "l"(a)); return f;
}

// Scratch (device globals; fp16 fragment-major, half2 packed along K)
__device__ uint32_t g_wfh [NCHUNKS*4096];  // -w   64x128: block b = mr*8 + kc(8)
__device__ uint32_t g_qefh[NCHUNKS*4096];  // qe   64x128: same blocks
__device__ uint32_t g_krfh[NCHUNKS*4096];  // krT 128x64 : block b = cr*4 + kc(4)
__device__ uint32_t g_Afh [NCHUNKS*2048];  // Aqk  64x64 : block b = mr*4 + kc(4)
__device__ __half   g_uh  [BHT*SEQ*DVD];   // u fp16 [row][V]
__device__ float    g_egl [NCHUNKS];

#define P1_SMEM ((8704*2 + 4352 + 3*64)*4)

// ---------------------------------------------------------------------------
// Phase 1: per-chunk (2048 CTAs). Gram matmuls on fp16 mma; fp32 triangular
// solve with packed-f32x2 reduction (bit-exact fp32).
// ---------------------------------------------------------------------------
__global__ void __launch_bounds__(256, 2) p1_kernel(
    const float* __restrict__ q, const float* __restrict__ k,
    const float* __restrict__ v, const float* __restrict__ g,
    const float* __restrict__ beta)
{
    extern __shared__ float sm[];
    float* skT = sm;                 // [128][68] k transposed (normalized)
    float* sqT = skT + 8704;         // [128][68] q transposed; later: -w staged
    float* sA0 = sqT + 8704;         // [64][68]  strictly-lower A0 (fp32)
    float* seg = sA0 + 4352;         // [64] exp(cumsum g)
    float* sie = seg + 64;           // [64] 1/seg
    float* sb  = sie + 64;           // [64] beta
    __shared__ float sgr[BT];

    const int cid = blockIdx.x;
    const int bh  = cid / NCH, n = cid % NCH;
    const int rowbase = bh*SEQ + n*BT;
    const int t = threadIdx.x;
    const int lane = t & 31, wid = t >> 5;
    const int gq = lane >> 2, tig = lane & 3;

    if (t < BT) { sb[t] = beta[rowbase + t]; sgr[t] = g[rowbase + t]; }
    __syncthreads();
    if (t < 32) {
        float a = sgr[2*t], b = sgr[2*t+1];
        float s = a + b;
        #pragma unroll
        for (int o = 1; o < 32; o <<= 1) {
            float y = __shfl_up_sync(0xffffffffu, s, o);
            if (t >= o) s += y;
        }
        float gc1 = s, gc0 = s - b;
        seg[2*t  ] = __expf(gc0);  sie[2*t  ] = __expf(-gc0);
        seg[2*t+1] = __expf(gc1);  sie[2*t+1] = __expf(-gc1);
        if (t == 31) g_egl[cid] = seg[63];
    }
    // normalize rows of q,k; store transposed
    for (int r = wid; r < BT; r += 8) {
        const float* kp = k + (size_t)(rowbase + r)*DKD;
        const float* qp = q + (size_t)(rowbase + r)*DKD;
        float k0=kp[lane],k1=kp[lane+32],k2=kp[lane+64],k3=kp[lane+96];
        float q0=qp[lane],q1=qp[lane+32],q2=qp[lane+64],q3=qp[lane+96];
        float ssk = k0*k0+k1*k1+k2*k2+k3*k3;
        float ssq = q0*q0+q1*q1+q2*q2+q3*q3;
        #pragma unroll
        for (int o = 16; o; o >>= 1) {
            ssk += __shfl_xor_sync(0xffffffffu, ssk, o);
            ssq += __shfl_xor_sync(0xffffffffu, ssq, o);
        }
        float ik = 1.f/(sqrtf(ssk)+1e-6f);
        float iq = 0.08838834764831845f/(sqrtf(ssq)+1e-6f);  // K^-0.5 folded in
        skT[(lane    )*68+r]=k0*ik; skT[(lane+32)*68+r]=k1*ik;
        skT[(lane+64)*68+r]=k2*ik; skT[(lane+96)*68+r]=k3*ik;
        sqT[(lane    )*68+r]=q0*iq; sqT[(lane+32)*68+r]=q1*iq;
        sqT[(lane+64)*68+r]=q2*iq; sqT[(lane+96)*68+r]=q3*iq;
    }
    __syncthreads();

    // ---- warps 0-3: Aqk = q·k^T via mma -> g_Afh; then qef emit
    //      warps 4-7: A0  = k·k^T via mma -> sA0 (fp32, lower tri); then krf
    if (wid < 4) {
        const int mr = wid;
        const int i0 = 16*mr + gq, i8 = i0 + 8;
        float D[8][4];
        #pragma unroll
        for (int z = 0; z < 8; z++) { D[z][0]=0.f; D[z][1]=0.f; D[z][2]=0.f; D[z][3]=0.f; }
        #pragma unroll
        for (int kc = 0; kc < 8; kc++) {
            int kb = 16*kc;
            uint32_t a0 = h2(sqT[(kb+2*tig  )*68+i0], sqT[(kb+2*tig+1)*68+i0]);
            uint32_t a1 = h2(sqT[(kb+2*tig  )*68+i8], sqT[(kb+2*tig+1)*68+i8]);
            uint32_t a2 = h2(sqT[(kb+2*tig+8)*68+i0], sqT[(kb+2*tig+9)*68+i0]);
            uint32_t a3 = h2(sqT[(kb+2*tig+8)*68+i8], sqT[(kb+2*tig+9)*68+i8]);
            #pragma unroll
            for (int nt = 0; nt < 8; nt++) {
                int jn = 8*nt + gq;
                uint32_t b0 = h2(skT[(kb+2*tig  )*68+jn], skT[(kb+2*tig+1)*68+jn]);
                uint32_t b1 = h2(skT[(kb+2*tig+8)*68+jn], skT[(kb+2*tig+9)*68+jn]);
                mma16(D[nt][0],D[nt][1],D[nt][2],D[nt][3], a0,a1,a2,a3, b0,b1);
            }
        }
        float s_i0 = seg[i0], s_i8 = seg[i8];
        #pragma unroll
        for (int c = 0; c < 4; c++) {
            int j0 = 16*c + 2*tig;
            float f00 = (j0   < i0) ? s_i0*sie[j0  ] : ((j0  ==i0)?1.f:0.f);
            float f01 = (j0+1 < i0) ? s_i0*sie[j0+1] : ((j0+1==i0)?1.f:0.f);
            float f80 = (j0   < i8) ? s_i8*sie[j0  ] : ((j0  ==i8)?1.f:0.f);
            float f81 = (j0+1 < i8) ? s_i8*sie[j0+1] : ((j0+1==i8)?1.f:0.f);
            float h00 = (j0+8 < i0) ? s_i0*sie[j0+8] : ((j0+8==i0)?1.f:0.f);
            float h01 = (j0+9 < i0) ? s_i0*sie[j0+9] : ((j0+9==i0)?1.f:0.f);
            float h80 = (j0+8 < i8) ? s_i8*sie[j0+8] : ((j0+8==i8)?1.f:0.f);
            float h81 = (j0+9 < i8) ? s_i8*sie[j0+9] : ((j0+9==i8)?1.f:0.f);
            uint4 o;
            o.x = h2(D[2*c  ][0]*f00, D[2*c  ][1]*f01);
            o.y = h2(D[2*c  ][2]*f80, D[2*c  ][3]*f81);
            o.z = h2(D[2*c+1][0]*h00, D[2*c+1][1]*h01);
            o.w = h2(D[2*c+1][2]*h80, D[2*c+1][3]*h81);
            *(uint4*)&g_Afh[(size_t)cid*2048 + (mr*4+c)*128 + lane*4] = o;
        }
        // qef emit
        for (int task = t; task < 1024; task += 128) {
            int b = task >> 5, l = task & 31;
            int ii = 16*(b>>3) + (l>>2), k0 = 16*(b&7) + (l&3)*2;
            float s0 = seg[ii], s1 = seg[ii+8];
            uint4 o;
            o.x = h2(sqT[(k0  )*68+ii  ]*s0, sqT[(k0+1)*68+ii  ]*s0);
            o.y = h2(sqT[(k0  )*68+ii+8]*s1, sqT[(k0+1)*68+ii+8]*s1);
            o.z = h2(sqT[(k0+8)*68+ii  ]*s0, sqT[(k0+9)*68+ii  ]*s0);
            o.w = h2(sqT[(k0+8)*68+ii+8]*s1, sqT[(k0+9)*68+ii+8]*s1);
            *(uint4*)&g_qefh[(size_t)cid*4096 + b*128 + l*4] = o;
        }
    } else {
        const int mr = wid - 4;
        const int i0 = 16*mr + gq, i8 = i0 + 8;
        float D[8][4];
        #pragma unroll
        for (int z = 0; z < 8; z++) { D[z][0]=0.f; D[z][1]=0.f; D[z][2]=0.f; D[z][3]=0.f; }
        #pragma unroll
        for (int kc = 0; kc < 8; kc++) {
            int kb = 16*kc;
            uint32_t a0 = h2(skT[(kb+2*tig  )*68+i0], skT[(kb+2*tig+1)*68+i0]);
            uint32_t a1 = h2(skT[(kb+2*tig  )*68+i8], skT[(kb+2*tig+1)*68+i8]);
            uint32_t a2 = h2(skT[(kb+2*tig+8)*68+i0], skT[(kb+2*tig+9)*68+i0]);
            uint32_t a3 = h2(skT[(kb+2*tig+8)*68+i8], skT[(kb+2*tig+9)*68+i8]);
            #pragma unroll
            for (int nt = 0; nt < 8; nt++) {
                int jn = 8*nt + gq;
                uint32_t b0 = h2(skT[(kb+2*tig  )*68+jn], skT[(kb+2*tig+1)*68+jn]);
                uint32_t b1 = h2(skT[(kb+2*tig+8)*68+jn], skT[(kb+2*tig+9)*68+jn]);
                mma16(D[nt][0],D[nt][1],D[nt][2],D[nt][3], a0,a1,a2,a3, b0,b1);
            }
        }
        // scale + store strict lower triangle (fp32)
        float bs0 = seg[i0]*sb[i0], bs8 = seg[i8]*sb[i8];
        #pragma unroll
        for (int nt = 0; nt < 8; nt++) {
            int j0 = 8*nt + 2*tig;
            if (j0   < i0) sA0[i0*68+j0  ] = D[nt][0]*bs0*sie[j0  ];
            if (j0+1 < i0) sA0[i0*68+j0+1] = D[nt][1]*bs0*sie[j0+1];
            if (j0   < i8) sA0[i8*68+j0  ] = D[nt][2]*bs8*sie[j0  ];
            if (j0+1 < i8) sA0[i8*68+j0+1] = D[nt][3]*bs8*sie[j0+1];
        }
        // krf emit
        float egl2 = seg[BT-1];
        for (int task = t - 128; task < 1024; task += 128) {
            int b = task >> 5, l = task & 31;
            int c0 = 16*(b>>2) + (l>>2), ii = 16*(b&3) + (l&3)*2;
            float e0 = egl2*sie[ii], e1 = egl2*sie[ii+1];
            float e8 = egl2*sie[ii+8], e9 = egl2*sie[ii+9];
            uint4 o;
            o.x = h2(skT[(c0  )*68+ii  ]*e0, skT[(c0  )*68+ii+1]*e1);
            o.y = h2(skT[(c0+8)*68+ii  ]*e0, skT[(c0+8)*68+ii+1]*e1);
            o.z = h2(skT[(c0  )*68+ii+8]*e8, skT[(c0  )*68+ii+9]*e9);
            o.w = h2(skT[(c0+8)*68+ii+8]*e8, skT[(c0+8)*68+ii+9]*e9);
            *(uint4*)&g_krfh[(size_t)cid*4096 + b*128 + l*4] = o;
        }
    }
    __syncthreads();   // sA0 ready; emits done before sqT is overwritten

    // Unit-lower triangular solve (fp32, packed f32x2 reduction; bit-exact)
    {
        u64 xp[32];   // packed pairs (x[2p], x[2p+1])
        if (t < 128) {
            #pragma unroll
            for (int p = 0; p < 32; p++)
                xp[p] = pkab(sb[2*p  ]*skT[t*68+2*p  ]*seg[2*p  ],
                             sb[2*p+1]*skT[t*68+2*p+1]*seg[2*p+1]);
        } else {
            const float* vp = v + (size_t)rowbase*DVD + (t - 128);
            #pragma unroll
            for (int p = 0; p < 32; p++)
                xp[p] = pkab(sb[2*p]*vp[(2*p)*DVD], sb[2*p+1]*vp[(2*p+1)*DVD]);
        }
        #pragma unroll
        for (int i = 1; i < 64; i++) {
            u64 s0 = 0ull, s1 = 0ull;
            int j = 0;
            #pragma unroll
            for (; j + 4 <= i; j += 4) {
                ulonglong2 av = *(const ulonglong2*)&sA0[i*68+j];
                s0 = fma2(av.x, xp[(j>>1)    ], s0);
                s1 = fma2(av.y, xp[(j>>1) + 1], s1);
            }
            if (i - j >= 2) {
                u64 av = *(const u64*)&sA0[i*68+j];
                s0 = fma2(av, xp[j>>1], s0);
                j += 2;
            }
            float2 p0 = up2(s0), p1 = up2(s1);
            float s = (p0.x + p0.y) + (p1.x + p1.y);
            if (i & 1) {
                // leftover even element j = i-1 (lo half of xp[(i-1)/2])
                float2 xl = up2(xp[(i-1) >> 1]);
                s += sA0[i*68 + (i-1)] * xl.x;
                float2 cur = up2(xp[i >> 1]);
                cur.y -= s;
                xp[i >> 1] = pkab(cur.x, cur.y);
            } else {
                float2 cur = up2(xp[i >> 1]);
                cur.x -= s;
                xp[i >> 1] = pkab(cur.x, cur.y);
            }
        }
        if (t < 128) {
            #pragma unroll
            for (int p = 0; p < 32; p++) {
                float2 xv = up2(xp[p]);
                *(float2*)&sqT[t*68 + 2*p] = make_float2(-xv.x, -xv.y);  // stage NEGATED w
            }
        } else {
            #pragma unroll
            for (int p = 0; p < 32; p++) {
                float2 xv = up2(xp[p]);
                __half2* dst = (__half2*)&g_uh[(size_t)(rowbase+2*p)*DVD + (t-128)];
                g_uh[(size_t)(rowbase+2*p  )*DVD + (t-128)] = __float2half_rn(xv.x);
                g_uh[(size_t)(rowbase+2*p+1)*DVD + (t-128)] = __float2half_rn(xv.y);
                (void)dst;
            }
        }
    }
    __syncthreads();

    // -w fragment emit (all 256 threads)
    for (int task = t; task < 1024; task += 256) {
        int b = task >> 5, l = task & 31;
        int i0 = 16*(b>>3) + (l>>2), k0 = 16*(b&7) + (l&3)*2;
        uint4 o;
        o.x = h2(sqT[(k0  )*68+i0  ], sqT[(k0+1)*68+i0  ]);
        o.y = h2(sqT[(k0  )*68+i0+8], sqT[(k0+1)*68+i0+8]);
        o.z = h2(sqT[(k0+8)*68+i0  ], sqT[(k0+9)*68+i0  ]);
        o.w = h2(sqT[(k0+8)*68+i0+8], sqT[(k0+9)*68+i0+8]);
        *(uint4*)&g_wfh[(size_t)cid*4096 + b*128 + l*4] = o;
    }
}

// ---------------------------------------------------------------------------
// Phase 2: fp16 mma recurrence, R8/R10 proven pipeline (grid 128, slices of 16).
// Double-buffered sS/svn; ONE full barrier per step + v-warps-only named bar.
// o-warps run one step behind (carry qe@S partial + Aqk frags).
// ---------------------------------------------------------------------------
__global__ void __launch_bounds__(256, 1) p2_kernel(float* __restrict__ out, int write_sf)
{
    __shared__ uint32_t sSb [2][16*68];   // S mirror, double buffered
    __shared__ uint32_t svnb[2][16*36];   // v_new, double buffered
    __shared__ float    segl[NCH];

    const int t = threadIdx.x;
    const int w = t >> 5, l = t & 31, g = l >> 2, tig = l & 3;
    const bool isv = (w < 4);
    const int mr = w & 3;
    const int bh = blockIdx.x >> 3;
    const int vb = (blockIdx.x & 7) * 16;

    for (int i = t; i < 16*68; i += 256) sSb[0][i] = 0u;
    if (t < NCH) segl[t] = g_egl[bh*NCH + t];
    __syncthreads();

    float S[16];                       // v-warps: persistent fp32 state strip
    #pragma unroll
    for (int i = 0; i < 16; i++) S[i] = 0.f;
    float C[8];                        // o-warps: carried o accumulator
    uint4 AF[4];                       // o-warps: carried Aqk frags (prev step)
    uint4 A[8];                        // L1 A frags (prefetched)
    uint4 K[8];                        // v-warps: krT frags (prefetched)
    uint32_t ur[4];                    // v-warps: u half2 regs (prefetched)

    const uint32_t* aL1 = isv ? g_wfh : g_qefh;
    {
        const uint4* Ab = (const uint4*)(aL1 + (size_t)(bh*NCH)*4096) + (mr*8)*32 + l;
        #pragma unroll
        for (int j = 0; j < 8; j++) A[j] = Ab[j*32];
        if (isv) {
            const uint4* Kb = (const uint4*)(g_krfh + (size_t)(bh*NCH)*4096) + l;
            #pragma unroll
            for (int mt = 0; mt < 2; mt++)
                #pragma unroll
                for (int kc = 0; kc < 4; kc++)
                    K[mt*4+kc] = Kb[((2*mr+mt)*4 + kc)*32];
            const uint32_t* up = (const uint32_t*)(g_uh + (size_t)(bh*SEQ + 16*mr + g)*DVD + vb);
            ur[0] = up[tig]; ur[1] = up[4+tig];
            ur[2] = up[512+tig]; ur[3] = up[512+4+tig];
        }
    }

    for (int n = 0; n < NCH; n++) {
        const int cid = bh*NCH + n;
        const size_t rb = (size_t)bh*SEQ + (size_t)n*BT;
        const int cur = n & 1;
        uint32_t* sSr  = sSb[cur];
        uint32_t* sSw  = sSb[cur^1];
        uint32_t* svnw = svnb[cur];
        uint32_t* svno = svnb[cur^1];

        if (isv) {
            // ---- L1: v = u + (-w)@S over K=128
            float2 f0 = __half22float2(*(__half2*)&ur[0]);
            float2 f1 = __half22float2(*(__half2*)&ur[1]);
            float2 f2 = __half22float2(*(__half2*)&ur[2]);
            float2 f3 = __half22float2(*(__half2*)&ur[3]);
            float a0=f0.x,a1=f0.y,a4=f1.x,a5=f1.y,a2=f2.x,a3=f2.y,a6=f3.x,a7=f3.y;
            #pragma unroll
            for (int kc = 0; kc < 8; kc++) {
                uint32_t b00 = sSr[(g  )*68 + 8*kc     + tig];
                uint32_t b01 = sSr[(g  )*68 + 8*kc + 4 + tig];
                uint32_t b10 = sSr[(8+g)*68 + 8*kc     + tig];
                uint32_t b11 = sSr[(8+g)*68 + 8*kc + 4 + tig];
                mma16(a0,a1,a2,a3, A[kc].x,A[kc].y,A[kc].z,A[kc].w, b00,b01);
                mma16(a4,a5,a6,a7, A[kc].x,A[kc].y,A[kc].z,A[kc].w, b10,b11);
            }
            if (n + 1 < NCH) {   // prefetch next -w frags
                const uint4* Ab = (const uint4*)(g_wfh + (size_t)(cid+1)*4096) + (mr*8)*32 + l;
                #pragma unroll
                for (int j = 0; j < 8; j++) A[j] = Ab[j*32];
            }
            // publish v_new
            {
                __half* svnh = (__half*)svnw;
                int p0 = (16*mr + g) >> 1, hb = g & 1;
                svnh[((2*tig  )*36 + p0  )*2 + hb] = __float2half_rn(a0);
                svnh[((2*tig+1)*36 + p0  )*2 + hb] = __float2half_rn(a1);
                svnh[((2*tig  )*36 + p0+4)*2 + hb] = __float2half_rn(a2);
                svnh[((2*tig+1)*36 + p0+4)*2 + hb] = __float2half_rn(a3);
                svnh[((8+2*tig  )*36 + p0  )*2 + hb] = __float2half_rn(a4);
                svnh[((8+2*tig+1)*36 + p0  )*2 + hb] = __float2half_rn(a5);
                svnh[((8+2*tig  )*36 + p0+4)*2 + hb] = __float2half_rn(a6);
                svnh[((8+2*tig+1)*36 + p0+4)*2 + hb] = __float2half_rn(a7);
            }
            asm volatile("bar.sync 1, 128;" ::: "memory");   // v-warps only

            // ---- L3: S = egl*S + krT @ v_new
            {
                const float egl = segl[n];
                #pragma unroll
                for (int i = 0; i < 16; i++) S[i] *= egl;
                #pragma unroll
                for (int kc = 0; kc < 4; kc++) {
                    uint32_t b00 = svnw[(g  )*36 + 8*kc     + tig];
                    uint32_t b01 = svnw[(g  )*36 + 8*kc + 4 + tig];
                    uint32_t b10 = svnw[(8+g)*36 + 8*kc     + tig];
                    uint32_t b11 = svnw[(8+g)*36 + 8*kc + 4 + tig];
                    mma16(S[0], S[1], S[2], S[3],  K[kc  ].x,K[kc  ].y,K[kc  ].z,K[kc  ].w, b00,b01);
                    mma16(S[4], S[5], S[6], S[7],  K[kc  ].x,K[kc  ].y,K[kc  ].z,K[kc  ].w, b10,b11);
                    mma16(S[8], S[9], S[10],S[11], K[4+kc].x,K[4+kc].y,K[4+kc].z,K[4+kc].w, b00,b01);
                    mma16(S[12],S[13],S[14],S[15], K[4+kc].x,K[4+kc].y,K[4+kc].z,K[4+kc].w, b10,b11);
                }
                __half* sSh = (__half*)sSw;
                #pragma unroll
                for (int mt = 0; mt < 2; mt++) {
                    int r = 32*mr + 16*mt + g;
                    int p = r >> 1, hb2 = r & 1;
                    #pragma unroll
                    for (int nh = 0; nh < 2; nh++) {
                        int c0 = nh*8 + 2*tig;
                        const float* sp = S + mt*8 + nh*4;
                        sSh[((c0  )*68 + p  )*2 + hb2] = __float2half_rn(sp[0]);
                        sSh[((c0+1)*68 + p  )*2 + hb2] = __float2half_rn(sp[1]);
                        sSh[((c0  )*68 + p+4)*2 + hb2] = __float2half_rn(sp[2]);
                        sSh[((c0+1)*68 + p+4)*2 + hb2] = __float2half_rn(sp[3]);
                    }
                }
            }
            if (n + 1 < NCH) {   // prefetch next K, u
                const uint4* Kb = (const uint4*)(g_krfh + (size_t)(cid+1)*4096) + l;
                #pragma unroll
                for (int mt = 0; mt < 2; mt++)
                    #pragma unroll
                    for (int kc = 0; kc < 4; kc++)
                        K[mt*4+kc] = Kb[((2*mr+mt)*4 + kc)*32];
                const uint32_t* up = (const uint32_t*)(g_uh + (rb + BT + 16*mr + g)*DVD + vb);
                ur[0] = up[tig]; ur[1] = up[4+tig];
                ur[2] = up[512+tig]; ur[3] = up[512+4+tig];
            }
        } else {
            // ---- finish o(n-1): C += Aqk(n-1) @ v_new(n-1); store
            if (n > 0) {
                #pragma unroll
                for (int kc = 0; kc < 4; kc++) {
                    uint32_t b00 = svno[(g  )*36 + 8*kc     + tig];
                    uint32_t b01 = svno[(g  )*36 + 8*kc + 4 + tig];
                    uint32_t b10 = svno[(8+g)*36 + 8*kc     + tig];
                    uint32_t b11 = svno[(8+g)*36 + 8*kc + 4 + tig];
                    mma16(C[0],C[1],C[2],C[3], AF[kc].x,AF[kc].y,AF[kc].z,AF[kc].w, b00,b01);
                    mma16(C[4],C[5],C[6],C[7], AF[kc].x,AF[kc].y,AF[kc].z,AF[kc].w, b10,b11);
                }
                float* d0 = out + (rb - BT + 16*mr + g)*DVD + vb;
                float* d1 = d0 + 8*DVD;
                *(float2*)(d0 +     2*tig) = make_float2(C[0], C[1]);
                *(float2*)(d1 +     2*tig) = make_float2(C[2], C[3]);
                *(float2*)(d0 + 8 + 2*tig) = make_float2(C[4], C[5]);
                *(float2*)(d1 + 8 + 2*tig) = make_float2(C[6], C[7]);
            }
            // load this step's Aqk frags (used next step)
            {
                const uint4* Fb = (const uint4*)(g_Afh + (size_t)cid*2048) + (mr*4)*32 + l;
                #pragma unroll
                for (int kc = 0; kc < 4; kc++) AF[kc] = Fb[kc*32];
            }
            // ---- qe(n) @ S(n) into fresh C
            #pragma unroll
            for (int i = 0; i < 8; i++) C[i] = 0.f;
            #pragma unroll
            for (int kc = 0; kc < 8; kc++) {
                uint32_t b00 = sSr[(g  )*68 + 8*kc     + tig];
                uint32_t b01 = sSr[(g  )*68 + 8*kc + 4 + tig];
                uint32_t b10 = sSr[(8+g)*68 + 8*kc     + tig];
                uint32_t b11 = sSr[(8+g)*68 + 8*kc + 4 + tig];
                mma16(C[0],C[1],C[2],C[3], A[kc].x,A[kc].y,A[kc].z,A[kc].w, b00,b01);
                mma16(C[4],C[5],C[6],C[7], A[kc].x,A[kc].y,A[kc].z,A[kc].w, b10,b11);
            }
            if (n + 1 < NCH) {   // prefetch next qe frags
                const uint4* Ab = (const uint4*)(g_qefh + (size_t)(cid+1)*4096) + (mr*8)*32 + l;
                #pragma unroll
                for (int j = 0; j < 8; j++) A[j] = Ab[j*32];
            }
        }
        __syncthreads();   // publishes sS[cur^1] + svn[cur]; retires svn[cur^1]
    }

    // o epilogue: finish the last chunk
    if (!isv) {
        uint32_t* svno = svnb[(NCH-1) & 1];
        #pragma unroll
        for (int kc = 0; kc < 4; kc++) {
            uint32_t b00 = svno[(g  )*36 + 8*kc     + tig];
            uint32_t b01 = svno[(g  )*36 + 8*kc + 4 + tig];
            uint32_t b10 = svno[(8+g)*36 + 8*kc     + tig];
            uint32_t b11 = svno[(8+g)*36 + 8*kc + 4 + tig];
            mma16(C[0],C[1],C[2],C[3], AF[kc].x,AF[kc].y,AF[kc].z,AF[kc].w, b00,b01);
            mma16(C[4],C[5],C[6],C[7], AF[kc].x,AF[kc].y,AF[kc].z,AF[kc].w, b10,b11);
        }
        float* d0 = out + ((size_t)bh*SEQ + (size_t)(NCH-1)*BT + 16*mr + g)*DVD + vb;
        float* d1 = d0 + 8*DVD;
        *(float2*)(d0 +     2*tig) = make_float2(C[0], C[1]);
        *(float2*)(d1 +     2*tig) = make_float2(C[2], C[3]);
        *(float2*)(d0 + 8 + 2*tig) = make_float2(C[4], C[5]);
        *(float2*)(d1 + 8 + 2*tig) = make_float2(C[6], C[7]);
    }

    if (write_sf && isv) {
        float* base = out + OSZ + (size_t)bh*DKD*DVD + vb;
        #pragma unroll
        for (int mt = 0; mt < 2; mt++) {
            int r = 32*mr + 16*mt + g;
            #pragma unroll
            for (int nh = 0; nh < 2; nh++) {
                const float* sp = S + mt*8 + nh*4;
                *(float2*)(base + (size_t)(r    )*DVD + nh*8 + 2*tig) = make_float2(sp[0], sp[1]);
                *(float2*)(base + (size_t)(r + 8)*DVD + nh*8 + 2*tig) = make_float2(sp[2], sp[3]);
            }
        }
    }
}

// ---------------------------------------------------------------------------
extern "C" void kernel_launch(void* const* d_in, const int* in_sizes, int n_in,
                              void* d_out, int out_size)
{
    const float* q    = (const float*)d_in[0];
    const float* k    = (const float*)d_in[1];
    const float* v    = (const float*)d_in[2];
    const float* g    = (const float*)d_in[3];
    const float* beta = (const float*)d_in[4];
    float* out = (float*)d_out;

    cudaFuncSetAttribute(p1_kernel, cudaFuncAttributeMaxDynamicSharedMemorySize, P1_SMEM);

    p1_kernel<<<NCHUNKS, 256, P1_SMEM>>>(q, k, v, g, beta);

    int wsf = (out_size > OSZ) ? 1 : 0;
    p2_kernel<<<BHT*8, 256>>>(out, wsf);
}

// round 13
// speedup vs baseline: 1.1451x; 1.0638x over previous
#include <cuda_runtime.h>
#include <cuda_fp16.h>
#include <cstdint>

// Problem constants (fixed by setup_inputs)
#define SEQ  8192
#define DKD  128
#define DVD  128
#define BT   64
#define NCH  128          // SEQ/BT
#define BHT  16           // BB*HHD
#define NCHUNKS 2048      // BHT*NCH
#define OSZ  16777216     // BHT*SEQ*DVD  (size of o)

typedef unsigned long long u64;

// ---- fp16 helpers ----
__device__ __forceinline__ uint32_t h2(float lo, float hi) {
    __half2 h = __floats2half2_rn(lo, hi);
    return *reinterpret_cast<uint32_t*>(&h);
}
__device__ __forceinline__ void mma16(float& d0, float& d1, float& d2, float& d3,
    uint32_t a0, uint32_t a1, uint32_t a2, uint32_t a3, uint32_t b0, uint32_t b1) {
    asm("mma.sync.aligned.m16n8k16.row.col.f32.f16.f16.f32 "
        "{%0,%1,%2,%3},{%4,%5,%6,%7},{%8,%9},{%0,%1,%2,%3};"
        : "+f"(d0), "+f"(d1), "+f"(d2), "+f"(d3)
        : "r"(a0), "r"(a1), "r"(a2), "r"(a3), "r"(b0), "r"(b1));
}

// ---- packed f32x2 helpers (exact fp32 lanes) ----
__device__ __forceinline__ u64 pkab(float a, float b) {
    u64 r; asm("mov.b64 %0,{%1,%2};" : "=l"(r) : "f"(a), "f"(b)); return r;
}
__device__ __forceinline__ u64 fma2(u64 a, u64 b, u64 c) {
    u64 d; asm("fma.rn.f32x2 %0,%1,%2,%3;" : "=l"(d) : "l"(a), "l"(b), "l"(c)); return d;
}
__device__ __forceinline__ float2 up2(u64 a) {
    float2 f; asm("mov.b64 {%0,%1},%2;" : "=f"(f.x), "=f"(f.y) : "l"(a)); return f;
}

// Scratch (device globals; fp16 fragment-major, half2 packed along K)
__device__ uint32_t g_wfh [NCHUNKS*4096];  // -w   64x128: block b = mr*8 + kc(8)
__device__ uint32_t g_qefh[NCHUNKS*4096];  // qe   64x128: same blocks
__device__ uint32_t g_krfh[NCHUNKS*4096];  // krT 128x64 : block b = cr*4 + kc(4)
__device__ uint32_t g_Afh [NCHUNKS*2048];  // Aqk  64x64 : block b = mr*4 + kc(4)
__device__ __half   g_uh  [BHT*SEQ*DVD];   // u fp16 [row][V]
__device__ float    g_egl [NCHUNKS];

// p1 smem layout (floats): kh 4352 | qh/wh 4352 | skT 128*69 | sA0 64*68 | seg/sie/sb 192
#define P1_SMEM ((4352 + 4352 + 128*69 + 64*68 + 3*64)*4)

// ---------------------------------------------------------------------------
// Phase 1: per-chunk (2048 CTAs). q/k staged fp16 row-major (qh prescaled by
// seg) -> gram fragments + qe/wf emits are single-LDS relayouts. fp32 skT
// (stride 69, conflict-free) kept for the solve rhs + krf (precision parity).
// ---------------------------------------------------------------------------
__global__ void __launch_bounds__(256, 2) p1_kernel(
    const float* __restrict__ q, const float* __restrict__ k,
    const float* __restrict__ v, const float* __restrict__ g,
    const float* __restrict__ beta)
{
    extern __shared__ float sm[];
    __half* khh = (__half*)sm;              // [64][136] fp16 k_norm
    __half* qhh = (__half*)(sm + 4352);     // [64][136] fp16 q_norm*scale*seg
    __half* whh = (__half*)(sm + 4352);     // overlays qh after solve barrier
    float* skT = sm + 8704;                 // [128][69] fp32 k_norm transposed
    float* sA0 = skT + 128*69;              // [64][68]  strictly-lower A0 (fp32)
    float* seg = sA0 + 4352;                // [64] exp(cumsum g)
    float* sie = seg + 64;                  // [64] 1/seg
    float* sb  = sie + 64;                  // [64] beta
    __shared__ float sgr[BT];

    const int cid = blockIdx.x;
    const int bh  = cid / NCH, n = cid % NCH;
    const int rowbase = bh*SEQ + n*BT;
    const int t = threadIdx.x;
    const int lane = t & 31, wid = t >> 5;
    const int gq = lane >> 2, tig = lane & 3;

    if (t < BT) { sb[t] = beta[rowbase + t]; sgr[t] = g[rowbase + t]; }
    __syncthreads();
    if (t < 32) {
        float a = sgr[2*t], b = sgr[2*t+1];
        float s = a + b;
        #pragma unroll
        for (int o = 1; o < 32; o <<= 1) {
            float y = __shfl_up_sync(0xffffffffu, s, o);
            if (t >= o) s += y;
        }
        float gc1 = s, gc0 = s - b;
        seg[2*t  ] = __expf(gc0);  sie[2*t  ] = __expf(-gc0);
        seg[2*t+1] = __expf(gc1);  sie[2*t+1] = __expf(-gc1);
        if (t == 31) g_egl[cid] = seg[63];
    }
    __syncthreads();   // seg ready (norm prescales q by seg[r])

    // normalize rows; write fp16 row-major (pairs along K) + fp32 skT
    for (int r = wid; r < BT; r += 8) {
        const float2* kp = (const float2*)(k + (size_t)(rowbase + r)*DKD);
        const float2* qp = (const float2*)(q + (size_t)(rowbase + r)*DKD);
        float2 k0 = kp[lane], k1 = kp[lane+32];
        float2 q0 = qp[lane], q1 = qp[lane+32];
        float ssk = k0.x*k0.x + k0.y*k0.y + k1.x*k1.x + k1.y*k1.y;
        float ssq = q0.x*q0.x + q0.y*q0.y + q1.x*q1.x + q1.y*q1.y;
        #pragma unroll
        for (int o = 16; o; o >>= 1) {
            ssk += __shfl_xor_sync(0xffffffffu, ssk, o);
            ssq += __shfl_xor_sync(0xffffffffu, ssq, o);
        }
        float ik = 1.f/(sqrtf(ssk)+1e-6f);
        float iq = 0.08838834764831845f/(sqrtf(ssq)+1e-6f) * seg[r];  // scale*seg
        *(uint32_t*)&khh[r*136      + 2*lane] = h2(k0.x*ik, k0.y*ik);
        *(uint32_t*)&khh[r*136 + 64 + 2*lane] = h2(k1.x*ik, k1.y*ik);
        *(uint32_t*)&qhh[r*136      + 2*lane] = h2(q0.x*iq, q0.y*iq);
        *(uint32_t*)&qhh[r*136 + 64 + 2*lane] = h2(q1.x*iq, q1.y*iq);
        skT[(2*lane   )*69 + r] = k0.x*ik;
        skT[(2*lane+ 1)*69 + r] = k0.y*ik;
        skT[(2*lane+64)*69 + r] = k1.x*ik;
        skT[(2*lane+65)*69 + r] = k1.y*ik;
    }
    __syncthreads();

    // ---- warps 0-3: Aqk = (q*seg)·k^T via mma -> g_Afh (x sie_j mask); qef emit
    //      warps 4-7: A0  = k·k^T via mma -> sA0 (fp32, lower tri); krf emit
    if (wid < 4) {
        const int mr = wid;
        const int i0 = 16*mr + gq, i8 = i0 + 8;
        float D[8][4];
        #pragma unroll
        for (int z = 0; z < 8; z++) { D[z][0]=0.f; D[z][1]=0.f; D[z][2]=0.f; D[z][3]=0.f; }
        #pragma unroll
        for (int kc = 0; kc < 8; kc++) {
            int kb = 16*kc;
            uint32_t a0 = *(const uint32_t*)&qhh[i0*136 + kb + 2*tig];
            uint32_t a1 = *(const uint32_t*)&qhh[i8*136 + kb + 2*tig];
            uint32_t a2 = *(const uint32_t*)&qhh[i0*136 + kb + 2*tig + 8];
            uint32_t a3 = *(const uint32_t*)&qhh[i8*136 + kb + 2*tig + 8];
            #pragma unroll
            for (int nt = 0; nt < 8; nt++) {
                int jn = 8*nt + gq;
                uint32_t b0 = *(const uint32_t*)&khh[jn*136 + kb + 2*tig];
                uint32_t b1 = *(const uint32_t*)&khh[jn*136 + kb + 2*tig + 8];
                mma16(D[nt][0],D[nt][1],D[nt][2],D[nt][3], a0,a1,a2,a3, b0,b1);
            }
        }
        // Aqk scale: f(j,i) = (j<=i) ? sie[j] : 0   (seg_i absorbed in qh)
        #pragma unroll
        for (int c = 0; c < 4; c++) {
            int j0 = 16*c + 2*tig;
            float f00 = (j0   <= i0) ? sie[j0  ] : 0.f;
            float f01 = (j0+1 <= i0) ? sie[j0+1] : 0.f;
            float f80 = (j0   <= i8) ? sie[j0  ] : 0.f;
            float f81 = (j0+1 <= i8) ? sie[j0+1] : 0.f;
            float h00 = (j0+8 <= i0) ? sie[j0+8] : 0.f;
            float h01 = (j0+9 <= i0) ? sie[j0+9] : 0.f;
            float h80 = (j0+8 <= i8) ? sie[j0+8] : 0.f;
            float h81 = (j0+9 <= i8) ? sie[j0+9] : 0.f;
            uint4 o;
            o.x = h2(D[2*c  ][0]*f00, D[2*c  ][1]*f01);
            o.y = h2(D[2*c  ][2]*f80, D[2*c  ][3]*f81);
            o.z = h2(D[2*c+1][0]*h00, D[2*c+1][1]*h01);
            o.w = h2(D[2*c+1][2]*h80, D[2*c+1][3]*h81);
            *(uint4*)&g_Afh[(size_t)cid*2048 + (mr*4+c)*128 + lane*4] = o;
        }
        // qef emit: pure relayout of prescaled qh
        for (int task = t; task < 1024; task += 128) {
            int b = task >> 5, l = task & 31;
            int ii = 16*(b>>3) + (l>>2), k0 = 16*(b&7) + (l&3)*2;
            uint4 o;
            o.x = *(const uint32_t*)&qhh[(ii  )*136 + k0    ];
            o.y = *(const uint32_t*)&qhh[(ii+8)*136 + k0    ];
            o.z = *(const uint32_t*)&qhh[(ii  )*136 + k0 + 8];
            o.w = *(const uint32_t*)&qhh[(ii+8)*136 + k0 + 8];
            *(uint4*)&g_qefh[(size_t)cid*4096 + b*128 + l*4] = o;
        }
    } else {
        const int mr = wid - 4;
        const int i0 = 16*mr + gq, i8 = i0 + 8;
        float D[8][4];
        #pragma unroll
        for (int z = 0; z < 8; z++) { D[z][0]=0.f; D[z][1]=0.f; D[z][2]=0.f; D[z][3]=0.f; }
        #pragma unroll
        for (int kc = 0; kc < 8; kc++) {
            int kb = 16*kc;
            uint32_t a0 = *(const uint32_t*)&khh[i0*136 + kb + 2*tig];
            uint32_t a1 = *(const uint32_t*)&khh[i8*136 + kb + 2*tig];
            uint32_t a2 = *(const uint32_t*)&khh[i0*136 + kb + 2*tig + 8];
            uint32_t a3 = *(const uint32_t*)&khh[i8*136 + kb + 2*tig + 8];
            #pragma unroll
            for (int nt = 0; nt < 8; nt++) {
                int jn = 8*nt + gq;
                uint32_t b0 = *(const uint32_t*)&khh[jn*136 + kb + 2*tig];
                uint32_t b1 = *(const uint32_t*)&khh[jn*136 + kb + 2*tig + 8];
                mma16(D[nt][0],D[nt][1],D[nt][2],D[nt][3], a0,a1,a2,a3, b0,b1);
            }
        }
        // scale + store strict lower triangle (fp32)
        float bs0 = seg[i0]*sb[i0], bs8 = seg[i8]*sb[i8];
        #pragma unroll
        for (int nt = 0; nt < 8; nt++) {
            int j0 = 8*nt + 2*tig;
            if (j0   < i0) sA0[i0*68+j0  ] = D[nt][0]*bs0*sie[j0  ];
            if (j0+1 < i0) sA0[i0*68+j0+1] = D[nt][1]*bs0*sie[j0+1];
            if (j0   < i8) sA0[i8*68+j0  ] = D[nt][2]*bs8*sie[j0  ];
            if (j0+1 < i8) sA0[i8*68+j0+1] = D[nt][3]*bs8*sie[j0+1];
        }
        // krf emit (from fp32 skT, stride 69)
        float egl2 = seg[BT-1];
        for (int task = t - 128; task < 1024; task += 128) {
            int b = task >> 5, l = task & 31;
            int c0 = 16*(b>>2) + (l>>2), ii = 16*(b&3) + (l&3)*2;
            float e0 = egl2*sie[ii], e1 = egl2*sie[ii+1];
            float e8 = egl2*sie[ii+8], e9 = egl2*sie[ii+9];
            uint4 o;
            o.x = h2(skT[(c0  )*69+ii  ]*e0, skT[(c0  )*69+ii+1]*e1);
            o.y = h2(skT[(c0+8)*69+ii  ]*e0, skT[(c0+8)*69+ii+1]*e1);
            o.z = h2(skT[(c0  )*69+ii+8]*e8, skT[(c0  )*69+ii+9]*e9);
            o.w = h2(skT[(c0+8)*69+ii+8]*e8, skT[(c0+8)*69+ii+9]*e9);
            *(uint4*)&g_krfh[(size_t)cid*4096 + b*128 + l*4] = o;
        }
    }
    __syncthreads();   // sA0 ready; qh reads done before whh overlays it

    // Unit-lower triangular solve (fp32, packed f32x2; rhs from fp32 skT)
    {
        u64 xp[32];   // packed pairs (x[2p], x[2p+1])
        if (t < 128) {
            #pragma unroll
            for (int p = 0; p < 32; p++)
                xp[p] = pkab(sb[2*p  ]*skT[t*69+2*p  ]*seg[2*p  ],
                             sb[2*p+1]*skT[t*69+2*p+1]*seg[2*p+1]);
        } else {
            const float* vp = v + (size_t)rowbase*DVD + (t - 128);
            #pragma unroll
            for (int p = 0; p < 32; p++)
                xp[p] = pkab(sb[2*p]*vp[(2*p)*DVD], sb[2*p+1]*vp[(2*p+1)*DVD]);
        }
        #pragma unroll
        for (int i = 1; i < 64; i++) {
            u64 s0 = 0ull, s1 = 0ull;
            int j = 0;
            #pragma unroll
            for (; j + 4 <= i; j += 4) {
                ulonglong2 av = *(const ulonglong2*)&sA0[i*68+j];
                s0 = fma2(av.x, xp[(j>>1)    ], s0);
                s1 = fma2(av.y, xp[(j>>1) + 1], s1);
            }
            if (i - j >= 2) {
                u64 av = *(const u64*)&sA0[i*68+j];
                s0 = fma2(av, xp[j>>1], s0);
                j += 2;
            }
            float2 p0 = up2(s0), p1 = up2(s1);
            float s = (p0.x + p0.y) + (p1.x + p1.y);
            if (i & 1) {
                float2 xl = up2(xp[(i-1) >> 1]);
                s += sA0[i*68 + (i-1)] * xl.x;
                float2 cur = up2(xp[i >> 1]);
                cur.y -= s;
                xp[i >> 1] = pkab(cur.x, cur.y);
            } else {
                float2 cur = up2(xp[i >> 1]);
                cur.x -= s;
                xp[i >> 1] = pkab(cur.x, cur.y);
            }
        }
        if (t < 128) {
            #pragma unroll
            for (int p = 0; p < 32; p++) {
                float2 xv = up2(xp[p]);
                whh[(2*p  )*136 + t] = __float2half_rn(-xv.x);   // stage NEGATED w (fp16)
                whh[(2*p+1)*136 + t] = __float2half_rn(-xv.y);
            }
        } else {
            #pragma unroll
            for (int p = 0; p < 32; p++) {
                float2 xv = up2(xp[p]);
                g_uh[(size_t)(rowbase+2*p  )*DVD + (t-128)] = __float2half_rn(xv.x);
                g_uh[(size_t)(rowbase+2*p+1)*DVD + (t-128)] = __float2half_rn(xv.y);
            }
        }
    }
    __syncthreads();

    // -w fragment emit: pure relayout of whh
    for (int task = t; task < 1024; task += 256) {
        int b = task >> 5, l = task & 31;
        int i0 = 16*(b>>3) + (l>>2), k0 = 16*(b&7) + (l&3)*2;
        uint4 o;
        o.x = *(const uint32_t*)&whh[(i0  )*136 + k0    ];
        o.y = *(const uint32_t*)&whh[(i0+8)*136 + k0    ];
        o.z = *(const uint32_t*)&whh[(i0  )*136 + k0 + 8];
        o.w = *(const uint32_t*)&whh[(i0+8)*136 + k0 + 8];
        *(uint4*)&g_wfh[(size_t)cid*4096 + b*128 + l*4] = o;
    }
}

// ---------------------------------------------------------------------------
// Phase 2: fp16 mma recurrence, R8/R10/R12 proven pipeline (UNCHANGED).
// ---------------------------------------------------------------------------
__global__ void __launch_bounds__(256, 1) p2_kernel(float* __restrict__ out, int write_sf)
{
    __shared__ uint32_t sSb [2][16*68];   // S mirror, double buffered
    __shared__ uint32_t svnb[2][16*36];   // v_new, double buffered
    __shared__ float    segl[NCH];

    const int t = threadIdx.x;
    const int w = t >> 5, l = t & 31, g = l >> 2, tig = l & 3;
    const bool isv = (w < 4);
    const int mr = w & 3;
    const int bh = blockIdx.x >> 3;
    const int vb = (blockIdx.x & 7) * 16;

    for (int i = t; i < 16*68; i += 256) sSb[0][i] = 0u;
    if (t < NCH) segl[t] = g_egl[bh*NCH + t];
    __syncthreads();

    float S[16];
    #pragma unroll
    for (int i = 0; i < 16; i++) S[i] = 0.f;
    float C[8];
    uint4 AF[4];
    uint4 A[8];
    uint4 K[8];
    uint32_t ur[4];

    const uint32_t* aL1 = isv ? g_wfh : g_qefh;
    {
        const uint4* Ab = (const uint4*)(aL1 + (size_t)(bh*NCH)*4096) + (mr*8)*32 + l;
        #pragma unroll
        for (int j = 0; j < 8; j++) A[j] = Ab[j*32];
        if (isv) {
            const uint4* Kb = (const uint4*)(g_krfh + (size_t)(bh*NCH)*4096) + l;
            #pragma unroll
            for (int mt = 0; mt < 2; mt++)
                #pragma unroll
                for (int kc = 0; kc < 4; kc++)
                    K[mt*4+kc] = Kb[((2*mr+mt)*4 + kc)*32];
            const uint32_t* up = (const uint32_t*)(g_uh + (size_t)(bh*SEQ + 16*mr + g)*DVD + vb);
            ur[0] = up[tig]; ur[1] = up[4+tig];
            ur[2] = up[512+tig]; ur[3] = up[512+4+tig];
        }
    }

    for (int n = 0; n < NCH; n++) {
        const int cid = bh*NCH + n;
        const size_t rb = (size_t)bh*SEQ + (size_t)n*BT;
        const int cur = n & 1;
        uint32_t* sSr  = sSb[cur];
        uint32_t* sSw  = sSb[cur^1];
        uint32_t* svnw = svnb[cur];
        uint32_t* svno = svnb[cur^1];

        if (isv) {
            float2 f0 = __half22float2(*(__half2*)&ur[0]);
            float2 f1 = __half22float2(*(__half2*)&ur[1]);
            float2 f2 = __half22float2(*(__half2*)&ur[2]);
            float2 f3 = __half22float2(*(__half2*)&ur[3]);
            float a0=f0.x,a1=f0.y,a4=f1.x,a5=f1.y,a2=f2.x,a3=f2.y,a6=f3.x,a7=f3.y;
            #pragma unroll
            for (int kc = 0; kc < 8; kc++) {
                uint32_t b00 = sSr[(g  )*68 + 8*kc     + tig];
                uint32_t b01 = sSr[(g  )*68 + 8*kc + 4 + tig];
                uint32_t b10 = sSr[(8+g)*68 + 8*kc     + tig];
                uint32_t b11 = sSr[(8+g)*68 + 8*kc + 4 + tig];
                mma16(a0,a1,a2,a3, A[kc].x,A[kc].y,A[kc].z,A[kc].w, b00,b01);
                mma16(a4,a5,a6,a7, A[kc].x,A[kc].y,A[kc].z,A[kc].w, b10,b11);
            }
            if (n + 1 < NCH) {
                const uint4* Ab = (const uint4*)(g_wfh + (size_t)(cid+1)*4096) + (mr*8)*32 + l;
                #pragma unroll
                for (int j = 0; j < 8; j++) A[j] = Ab[j*32];
            }
            {
                __half* svnh = (__half*)svnw;
                int p0 = (16*mr + g) >> 1, hb = g & 1;
                svnh[((2*tig  )*36 + p0  )*2 + hb] = __float2half_rn(a0);
                svnh[((2*tig+1)*36 + p0  )*2 + hb] = __float2half_rn(a1);
                svnh[((2*tig  )*36 + p0+4)*2 + hb] = __float2half_rn(a2);
                svnh[((2*tig+1)*36 + p0+4)*2 + hb] = __float2half_rn(a3);
                svnh[((8+2*tig  )*36 + p0  )*2 + hb] = __float2half_rn(a4);
                svnh[((8+2*tig+1)*36 + p0  )*2 + hb] = __float2half_rn(a5);
                svnh[((8+2*tig  )*36 + p0+4)*2 + hb] = __float2half_rn(a6);
                svnh[((8+2*tig+1)*36 + p0+4)*2 + hb] = __float2half_rn(a7);
            }
            asm volatile("bar.sync 1, 128;" ::: "memory");

            {
                const float egl = segl[n];
                #pragma unroll
                for (int i = 0; i < 16; i++) S[i] *= egl;
                #pragma unroll
                for (int kc = 0; kc < 4; kc++) {
                    uint32_t b00 = svnw[(g  )*36 + 8*kc     + tig];
                    uint32_t b01 = svnw[(g  )*36 + 8*kc + 4 + tig];
                    uint32_t b10 = svnw[(8+g)*36 + 8*kc     + tig];
                    uint32_t b11 = svnw[(8+g)*36 + 8*kc + 4 + tig];
                    mma16(S[0], S[1], S[2], S[3],  K[kc  ].x,K[kc  ].y,K[kc  ].z,K[kc  ].w, b00,b01);
                    mma16(S[4], S[5], S[6], S[7],  K[kc  ].x,K[kc  ].y,K[kc  ].z,K[kc  ].w, b10,b11);
                    mma16(S[8], S[9], S[10],S[11], K[4+kc].x,K[4+kc].y,K[4+kc].z,K[4+kc].w, b00,b01);
                    mma16(S[12],S[13],S[14],S[15], K[4+kc].x,K[4+kc].y,K[4+kc].z,K[4+kc].w, b10,b11);
                }
                __half* sSh = (__half*)sSw;
                #pragma unroll
                for (int mt = 0; mt < 2; mt++) {
                    int r = 32*mr + 16*mt + g;
                    int p = r >> 1, hb2 = r & 1;
                    #pragma unroll
                    for (int nh = 0; nh < 2; nh++) {
                        int c0 = nh*8 + 2*tig;
                        const float* sp = S + mt*8 + nh*4;
                        sSh[((c0  )*68 + p  )*2 + hb2] = __float2half_rn(sp[0]);
                        sSh[((c0+1)*68 + p  )*2 + hb2] = __float2half_rn(sp[1]);
                        sSh[((c0  )*68 + p+4)*2 + hb2] = __float2half_rn(sp[2]);
                        sSh[((c0+1)*68 + p+4)*2 + hb2] = __float2half_rn(sp[3]);
                    }
                }
            }
            if (n + 1 < NCH) {
                const uint4* Kb = (const uint4*)(g_krfh + (size_t)(cid+1)*4096) + l;
                #pragma unroll
                for (int mt = 0; mt < 2; mt++)
                    #pragma unroll
                    for (int kc = 0; kc < 4; kc++)
                        K[mt*4+kc] = Kb[((2*mr+mt)*4 + kc)*32];
                const uint32_t* up = (const uint32_t*)(g_uh + (rb + BT + 16*mr + g)*DVD + vb);
                ur[0] = up[tig]; ur[1] = up[4+tig];
                ur[2] = up[512+tig]; ur[3] = up[512+4+tig];
            }
        } else {
            if (n > 0) {
                #pragma unroll
                for (int kc = 0; kc < 4; kc++) {
                    uint32_t b00 = svno[(g  )*36 + 8*kc     + tig];
                    uint32_t b01 = svno[(g  )*36 + 8*kc + 4 + tig];
                    uint32_t b10 = svno[(8+g)*36 + 8*kc     + tig];
                    uint32_t b11 = svno[(8+g)*36 + 8*kc + 4 + tig];
                    mma16(C[0],C[1],C[2],C[3], AF[kc].x,AF[kc].y,AF[kc].z,AF[kc].w, b00,b01);
                    mma16(C[4],C[5],C[6],C[7], AF[kc].x,AF[kc].y,AF[kc].z,AF[kc].w, b10,b11);
                }
                float* d0 = out + (rb - BT + 16*mr + g)*DVD + vb;
                float* d1 = d0 + 8*DVD;
                *(float2*)(d0 +     2*tig) = make_float2(C[0], C[1]);
                *(float2*)(d1 +     2*tig) = make_float2(C[2], C[3]);
                *(float2*)(d0 + 8 + 2*tig) = make_float2(C[4], C[5]);
                *(float2*)(d1 + 8 + 2*tig) = make_float2(C[6], C[7]);
            }
            {
                const uint4* Fb = (const uint4*)(g_Afh + (size_t)cid*2048) + (mr*4)*32 + l;
                #pragma unroll
                for (int kc = 0; kc < 4; kc++) AF[kc] = Fb[kc*32];
            }
            #pragma unroll
            for (int i = 0; i < 8; i++) C[i] = 0.f;
            #pragma unroll
            for (int kc = 0; kc < 8; kc++) {
                uint32_t b00 = sSr[(g  )*68 + 8*kc     + tig];
                uint32_t b01 = sSr[(g  )*68 + 8*kc + 4 + tig];
                uint32_t b10 = sSr[(8+g)*68 + 8*kc     + tig];
                uint32_t b11 = sSr[(8+g)*68 + 8*kc + 4 + tig];
                mma16(C[0],C[1],C[2],C[3], A[kc].x,A[kc].y,A[kc].z,A[kc].w, b00,b01);
                mma16(C[4],C[5],C[6],C[7], A[kc].x,A[kc].y,A[kc].z,A[kc].w, b10,b11);
            }
            if (n + 1 < NCH) {
                const uint4* Ab = (const uint4*)(g_qefh + (size_t)(cid+1)*4096) + (mr*8)*32 + l;
                #pragma unroll
                for (int j = 0; j < 8; j++) A[j] = Ab[j*32];
            }
        }
        __syncthreads();
    }

    if (!isv) {
        uint32_t* svno = svnb[(NCH-1) & 1];
        #pragma unroll
        for (int kc = 0; kc < 4; kc++) {
            uint32_t b00 = svno[(g  )*36 + 8*kc     + tig];
            uint32_t b01 = svno[(g  )*36 + 8*kc + 4 + tig];
            uint32_t b10 = svno[(8+g)*36 + 8*kc     + tig];
            uint32_t b11 = svno[(8+g)*36 + 8*kc + 4 + tig];
            mma16(C[0],C[1],C[2],C[3], AF[kc].x,AF[kc].y,AF[kc].z,AF[kc].w, b00,b01);
            mma16(C[4],C[5],C[6],C[7], AF[kc].x,AF[kc].y,AF[kc].z,AF[kc].w, b10,b11);
        }
        float* d0 = out + ((size_t)bh*SEQ + (size_t)(NCH-1)*BT + 16*mr + g)*DVD + vb;
        float* d1 = d0 + 8*DVD;
        *(float2*)(d0 +     2*tig) = make_float2(C[0], C[1]);
        *(float2*)(d1 +     2*tig) = make_float2(C[2], C[3]);
        *(float2*)(d0 + 8 + 2*tig) = make_float2(C[4], C[5]);
        *(float2*)(d1 + 8 + 2*tig) = make_float2(C[6], C[7]);
    }

    if (write_sf && isv) {
        float* base = out + OSZ + (size_t)bh*DKD*DVD + vb;
        #pragma unroll
        for (int mt = 0; mt < 2; mt++) {
            int r = 32*mr + 16*mt + g;
            #pragma unroll
            for (int nh = 0; nh < 2; nh++) {
                const float* sp = S + mt*8 + nh*4;
                *(float2*)(base + (size_t)(r    )*DVD + nh*8 + 2*tig) = make_float2(sp[0], sp[1]);
                *(float2*)(base + (size_t)(r + 8)*DVD + nh*8 + 2*tig) = make_float2(sp[2], sp[3]);
            }
        }
    }
}

// ---------------------------------------------------------------------------
extern "C" void kernel_launch(void* const* d_in, const int* in_sizes, int n_in,
                              void* d_out, int out_size)
{
    const float* q    = (const float*)d_in[0];
    const float* k    = (const float*)d_in[1];
    const float* v    = (const float*)d_in[2];
    const float* g    = (const float*)d_in[3];
    const float* beta = (const float*)d_in[4];
    float* out = (float*)d_out;

    cudaFuncSetAttribute(p1_kernel, cudaFuncAttributeMaxDynamicSharedMemorySize, P1_SMEM);

    p1_kernel<<<NCHUNKS, 256, P1_SMEM>>>(q, k, v, g, beta);

    int wsf = (out_size > OSZ) ? 1 : 0;
    p2_kernel<<<BHT*8, 256>>>(out, wsf);
}

// round 15
// speedup vs baseline: 1.1477x; 1.0022x over previous
#include <cuda_runtime.h>
#include <cuda_fp16.h>
#include <cstdint>

// Problem constants (fixed by setup_inputs)
#define SEQ  8192
#define DKD  128
#define DVD  128
#define BT   64
#define NCH  128          // SEQ/BT
#define BHT  16           // BB*HHD
#define NCHUNKS 2048      // BHT*NCH
#define OSZ  16777216     // BHT*SEQ*DVD  (size of o)

typedef unsigned long long u64;

// ---- fp16 helpers ----
__device__ __forceinline__ uint32_t h2(float lo, float hi) {
    __half2 h = __floats2half2_rn(lo, hi);
    return *reinterpret_cast<uint32_t*>(&h);
}
__device__ __forceinline__ void mma16(float& d0, float& d1, float& d2, float& d3,
    uint32_t a0, uint32_t a1, uint32_t a2, uint32_t a3, uint32_t b0, uint32_t b1) {
    asm("mma.sync.aligned.m16n8k16.row.col.f32.f16.f16.f32 "
        "{%0,%1,%2,%3},{%4,%5,%6,%7},{%8,%9},{%0,%1,%2,%3};"
        : "+f"(d0), "+f"(d1), "+f"(d2), "+f"(d3)
        : "r"(a0), "r"(a1), "r"(a2), "r"(a3), "r"(b0), "r"(b1));
}

// ---- packed f32x2 helpers (exact fp32 lanes) ----
__device__ __forceinline__ u64 pkab(float a, float b) {
    u64 r; asm("mov.b64 %0,{%1,%2};" : "=l"(r) : "f"(a), "f"(b)); return r;
}
__device__ __forceinline__ u64 fma2(u64 a, u64 b, u64 c) {
    u64 d; asm("fma.rn.f32x2 %0,%1,%2,%3;" : "=l"(d) : "l"(a), "l"(b), "l"(c)); return d;
}
__device__ __forceinline__ float2 up2(u64 a) {
    float2 f; asm("mov.b64 {%0,%1},%2;" : "=f"(f.x), "=f"(f.y) : "l"(a)); return f;
}

// Scratch (device globals; fp16 fragment-major, half2 packed along K)
__device__ uint32_t g_wfh [NCHUNKS*4096];  // -w   64x128: block b = mr*8 + kc(8)
__device__ uint32_t g_qefh[NCHUNKS*4096];  // qe   64x128: same blocks
__device__ uint32_t g_krfh[NCHUNKS*4096];  // krT 128x64 : block b = cr*4 + kc(4)
__device__ uint32_t g_Afh [NCHUNKS*2048];  // Aqk  64x64 : block b = mr*4 + kc(4)
__device__ __half   g_uh  [BHT*SEQ*DVD];   // u fp16 [row][V]
__device__ float    g_egl [NCHUNKS];
__device__ int      g_flag[NCHUNKS];       // chunk-done flags (producer/consumer)

// smem (floats): kh 4352 | qh/wh 4352 | skT 128*69 | sA0 64*68 | seg/sie/sb/sgr 256
// (round-14 bug: sgr was placed past the end; allocation now includes it)
#define FUSED_SMEM ((4352 + 4352 + 128*69 + 64*68 + 4*64)*4)

__global__ void zero_flags_kernel() {
    g_flag[blockIdx.x*256 + threadIdx.x] = 0;
}

__device__ __forceinline__ void wait_flag(int idx) {
    const int* p = g_flag + idx;
    int v;
    while (true) {
        asm volatile("ld.acquire.gpu.b32 %0, [%1];" : "=r"(v) : "l"(p) : "memory");
        if (v) break;
        __nanosleep(200);
    }
}

// ---------------------------------------------------------------------------
// p1 body: one chunk (round-13 math, banked) + release flag at the end.
// ---------------------------------------------------------------------------
__device__ void p1_body(float* sm, int cid, int rowbase,
    const float* __restrict__ q, const float* __restrict__ k,
    const float* __restrict__ v, const float* __restrict__ gg,
    const float* __restrict__ beta)
{
    __half* khh = (__half*)sm;              // [64][136] fp16 k_norm
    __half* qhh = (__half*)(sm + 4352);     // [64][136] fp16 q_norm*scale*seg
    __half* whh = (__half*)(sm + 4352);     // overlays qh after solve barrier
    float* skT = sm + 8704;                 // [128][69] fp32 k_norm transposed
    float* sA0 = skT + 128*69;              // [64][68]  strictly-lower A0 (fp32)
    float* seg = sA0 + 4352;                // [64] exp(cumsum g)
    float* sie = seg + 64;                  // [64] 1/seg
    float* sb  = sie + 64;                  // [64] beta
    float* sgr = sb + 64;                   // [64] raw g (WITHIN allocation now)

    const int t = threadIdx.x;
    const int lane = t & 31, wid = t >> 5;
    const int gq = lane >> 2, tig = lane & 3;

    if (t < BT) { sb[t] = beta[rowbase + t]; }
    if (t >= 128 && t < 128 + BT) { sgr[t-128] = gg[rowbase + (t-128)]; }
    __syncthreads();
    if (t < 32) {
        float a = sgr[2*t], b = sgr[2*t+1];
        float s = a + b;
        #pragma unroll
        for (int o = 1; o < 32; o <<= 1) {
            float y = __shfl_up_sync(0xffffffffu, s, o);
            if (t >= o) s += y;
        }
        float gc1 = s, gc0 = s - b;
        seg[2*t  ] = __expf(gc0);  sie[2*t  ] = __expf(-gc0);
        seg[2*t+1] = __expf(gc1);  sie[2*t+1] = __expf(-gc1);
        if (t == 31) g_egl[cid] = seg[63];
    }
    __syncthreads();   // seg ready

    // normalize rows; write fp16 row-major (pairs along K) + fp32 skT
    for (int r = wid; r < BT; r += 8) {
        const float2* kp = (const float2*)(k + (size_t)(rowbase + r)*DKD);
        const float2* qp = (const float2*)(q + (size_t)(rowbase + r)*DKD);
        float2 k0 = kp[lane], k1 = kp[lane+32];
        float2 q0 = qp[lane], q1 = qp[lane+32];
        float ssk = k0.x*k0.x + k0.y*k0.y + k1.x*k1.x + k1.y*k1.y;
        float ssq = q0.x*q0.x + q0.y*q0.y + q1.x*q1.x + q1.y*q1.y;
        #pragma unroll
        for (int o = 16; o; o >>= 1) {
            ssk += __shfl_xor_sync(0xffffffffu, ssk, o);
            ssq += __shfl_xor_sync(0xffffffffu, ssq, o);
        }
        float ik = 1.f/(sqrtf(ssk)+1e-6f);
        float iq = 0.08838834764831845f/(sqrtf(ssq)+1e-6f) * seg[r];  // scale*seg
        *(uint32_t*)&khh[r*136      + 2*lane] = h2(k0.x*ik, k0.y*ik);
        *(uint32_t*)&khh[r*136 + 64 + 2*lane] = h2(k1.x*ik, k1.y*ik);
        *(uint32_t*)&qhh[r*136      + 2*lane] = h2(q0.x*iq, q0.y*iq);
        *(uint32_t*)&qhh[r*136 + 64 + 2*lane] = h2(q1.x*iq, q1.y*iq);
        skT[(2*lane   )*69 + r] = k0.x*ik;
        skT[(2*lane+ 1)*69 + r] = k0.y*ik;
        skT[(2*lane+64)*69 + r] = k1.x*ik;
        skT[(2*lane+65)*69 + r] = k1.y*ik;
    }
    __syncthreads();

    // warps 0-3: Aqk via mma -> g_Afh; qef emit.  warps 4-7: A0 -> sA0; krf emit.
    if (wid < 4) {
        const int mr = wid;
        const int i0 = 16*mr + gq, i8 = i0 + 8;
        float D[8][4];
        #pragma unroll
        for (int z = 0; z < 8; z++) { D[z][0]=0.f; D[z][1]=0.f; D[z][2]=0.f; D[z][3]=0.f; }
        #pragma unroll
        for (int kc = 0; kc < 8; kc++) {
            int kb = 16*kc;
            uint32_t a0 = *(const uint32_t*)&qhh[i0*136 + kb + 2*tig];
            uint32_t a1 = *(const uint32_t*)&qhh[i8*136 + kb + 2*tig];
            uint32_t a2 = *(const uint32_t*)&qhh[i0*136 + kb + 2*tig + 8];
            uint32_t a3 = *(const uint32_t*)&qhh[i8*136 + kb + 2*tig + 8];
            #pragma unroll
            for (int nt = 0; nt < 8; nt++) {
                int jn = 8*nt + gq;
                uint32_t b0 = *(const uint32_t*)&khh[jn*136 + kb + 2*tig];
                uint32_t b1 = *(const uint32_t*)&khh[jn*136 + kb + 2*tig + 8];
                mma16(D[nt][0],D[nt][1],D[nt][2],D[nt][3], a0,a1,a2,a3, b0,b1);
            }
        }
        #pragma unroll
        for (int c = 0; c < 4; c++) {
            int j0 = 16*c + 2*tig;
            float f00 = (j0   <= i0) ? sie[j0  ] : 0.f;
            float f01 = (j0+1 <= i0) ? sie[j0+1] : 0.f;
            float f80 = (j0   <= i8) ? sie[j0  ] : 0.f;
            float f81 = (j0+1 <= i8) ? sie[j0+1] : 0.f;
            float h00 = (j0+8 <= i0) ? sie[j0+8] : 0.f;
            float h01 = (j0+9 <= i0) ? sie[j0+9] : 0.f;
            float h80 = (j0+8 <= i8) ? sie[j0+8] : 0.f;
            float h81 = (j0+9 <= i8) ? sie[j0+9] : 0.f;
            uint4 o;
            o.x = h2(D[2*c  ][0]*f00, D[2*c  ][1]*f01);
            o.y = h2(D[2*c  ][2]*f80, D[2*c  ][3]*f81);
            o.z = h2(D[2*c+1][0]*h00, D[2*c+1][1]*h01);
            o.w = h2(D[2*c+1][2]*h80, D[2*c+1][3]*h81);
            *(uint4*)&g_Afh[(size_t)cid*2048 + (mr*4+c)*128 + lane*4] = o;
        }
        for (int task = t; task < 1024; task += 128) {
            int b = task >> 5, l = task & 31;
            int ii = 16*(b>>3) + (l>>2), k0 = 16*(b&7) + (l&3)*2;
            uint4 o;
            o.x = *(const uint32_t*)&qhh[(ii  )*136 + k0    ];
            o.y = *(const uint32_t*)&qhh[(ii+8)*136 + k0    ];
            o.z = *(const uint32_t*)&qhh[(ii  )*136 + k0 + 8];
            o.w = *(const uint32_t*)&qhh[(ii+8)*136 + k0 + 8];
            *(uint4*)&g_qefh[(size_t)cid*4096 + b*128 + l*4] = o;
        }
    } else {
        const int mr = wid - 4;
        const int i0 = 16*mr + gq, i8 = i0 + 8;
        float D[8][4];
        #pragma unroll
        for (int z = 0; z < 8; z++) { D[z][0]=0.f; D[z][1]=0.f; D[z][2]=0.f; D[z][3]=0.f; }
        #pragma unroll
        for (int kc = 0; kc < 8; kc++) {
            int kb = 16*kc;
            uint32_t a0 = *(const uint32_t*)&khh[i0*136 + kb + 2*tig];
            uint32_t a1 = *(const uint32_t*)&khh[i8*136 + kb + 2*tig];
            uint32_t a2 = *(const uint32_t*)&khh[i0*136 + kb + 2*tig + 8];
            uint32_t a3 = *(const uint32_t*)&khh[i8*136 + kb + 2*tig + 8];
            #pragma unroll
            for (int nt = 0; nt < 8; nt++) {
                int jn = 8*nt + gq;
                uint32_t b0 = *(const uint32_t*)&khh[jn*136 + kb + 2*tig];
                uint32_t b1 = *(const uint32_t*)&khh[jn*136 + kb + 2*tig + 8];
                mma16(D[nt][0],D[nt][1],D[nt][2],D[nt][3], a0,a1,a2,a3, b0,b1);
            }
        }
        float bs0 = seg[i0]*sb[i0], bs8 = seg[i8]*sb[i8];
        #pragma unroll
        for (int nt = 0; nt < 8; nt++) {
            int j0 = 8*nt + 2*tig;
            if (j0   < i0) sA0[i0*68+j0  ] = D[nt][0]*bs0*sie[j0  ];
            if (j0+1 < i0) sA0[i0*68+j0+1] = D[nt][1]*bs0*sie[j0+1];
            if (j0   < i8) sA0[i8*68+j0  ] = D[nt][2]*bs8*sie[j0  ];
            if (j0+1 < i8) sA0[i8*68+j0+1] = D[nt][3]*bs8*sie[j0+1];
        }
        float egl2 = seg[BT-1];
        for (int task = t - 128; task < 1024; task += 128) {
            int b = task >> 5, l = task & 31;
            int c0 = 16*(b>>2) + (l>>2), ii = 16*(b&3) + (l&3)*2;
            float e0 = egl2*sie[ii], e1 = egl2*sie[ii+1];
            float e8 = egl2*sie[ii+8], e9 = egl2*sie[ii+9];
            uint4 o;
            o.x = h2(skT[(c0  )*69+ii  ]*e0, skT[(c0  )*69+ii+1]*e1);
            o.y = h2(skT[(c0+8)*69+ii  ]*e0, skT[(c0+8)*69+ii+1]*e1);
            o.z = h2(skT[(c0  )*69+ii+8]*e8, skT[(c0  )*69+ii+9]*e9);
            o.w = h2(skT[(c0+8)*69+ii+8]*e8, skT[(c0+8)*69+ii+9]*e9);
            *(uint4*)&g_krfh[(size_t)cid*4096 + b*128 + l*4] = o;
        }
    }
    __syncthreads();

    // Unit-lower triangular solve (fp32, packed f32x2)
    {
        u64 xp[32];
        if (t < 128) {
            #pragma unroll
            for (int p = 0; p < 32; p++)
                xp[p] = pkab(sb[2*p  ]*skT[t*69+2*p  ]*seg[2*p  ],
                             sb[2*p+1]*skT[t*69+2*p+1]*seg[2*p+1]);
        } else {
            const float* vp = v + (size_t)rowbase*DVD + (t - 128);
            #pragma unroll
            for (int p = 0; p < 32; p++)
                xp[p] = pkab(sb[2*p]*vp[(2*p)*DVD], sb[2*p+1]*vp[(2*p+1)*DVD]);
        }
        #pragma unroll
        for (int i = 1; i < 64; i++) {
            u64 s0 = 0ull, s1 = 0ull;
            int j = 0;
            #pragma unroll
            for (; j + 4 <= i; j += 4) {
                ulonglong2 av = *(const ulonglong2*)&sA0[i*68+j];
                s0 = fma2(av.x, xp[(j>>1)    ], s0);
                s1 = fma2(av.y, xp[(j>>1) + 1], s1);
            }
            if (i - j >= 2) {
                u64 av = *(const u64*)&sA0[i*68+j];
                s0 = fma2(av, xp[j>>1], s0);
                j += 2;
            }
            float2 p0 = up2(s0), p1 = up2(s1);
            float s = (p0.x + p0.y) + (p1.x + p1.y);
            if (i & 1) {
                float2 xl = up2(xp[(i-1) >> 1]);
                s += sA0[i*68 + (i-1)] * xl.x;
                float2 cur = up2(xp[i >> 1]);
                cur.y -= s;
                xp[i >> 1] = pkab(cur.x, cur.y);
            } else {
                float2 cur = up2(xp[i >> 1]);
                cur.x -= s;
                xp[i >> 1] = pkab(cur.x, cur.y);
            }
        }
        if (t < 128) {
            #pragma unroll
            for (int p = 0; p < 32; p++) {
                float2 xv = up2(xp[p]);
                whh[(2*p  )*136 + t] = __float2half_rn(-xv.x);   // NEGATED w
                whh[(2*p+1)*136 + t] = __float2half_rn(-xv.y);
            }
        } else {
            #pragma unroll
            for (int p = 0; p < 32; p++) {
                float2 xv = up2(xp[p]);
                g_uh[(size_t)(rowbase+2*p  )*DVD + (t-128)] = __float2half_rn(xv.x);
                g_uh[(size_t)(rowbase+2*p+1)*DVD + (t-128)] = __float2half_rn(xv.y);
            }
        }
    }
    __syncthreads();

    // -w fragment emit
    for (int task = t; task < 1024; task += 256) {
        int b = task >> 5, l = task & 31;
        int i0 = 16*(b>>3) + (l>>2), k0 = 16*(b&7) + (l&3)*2;
        uint4 o;
        o.x = *(const uint32_t*)&whh[(i0  )*136 + k0    ];
        o.y = *(const uint32_t*)&whh[(i0+8)*136 + k0    ];
        o.z = *(const uint32_t*)&whh[(i0  )*136 + k0 + 8];
        o.w = *(const uint32_t*)&whh[(i0+8)*136 + k0 + 8];
        *(uint4*)&g_wfh[(size_t)cid*4096 + b*128 + l*4] = o;
    }

    // publish chunk-done flag (release)
    __syncthreads();
    if (t == 0) {
        __threadfence();
        asm volatile("st.global.release.gpu.b32 [%0], %1;"
                     :: "l"(g_flag + cid), "r"(1) : "memory");
    }
}

// ---------------------------------------------------------------------------
// p2 body: R12/R13-proven recurrence pipeline, gated on producer flags.
// ---------------------------------------------------------------------------
__device__ void p2_body(float* smraw, int p2i, float* __restrict__ out, int write_sf)
{
    uint32_t* sSb  = (uint32_t*)smraw;        // [2][16*68]
    uint32_t* svnb = sSb + 2*16*68;           // [2][16*36]

    const int t = threadIdx.x;
    const int w = t >> 5, l = t & 31, g = l >> 2, tig = l & 3;
    const bool isv = (w < 4);
    const int mr = w & 3;
    const int bh = p2i >> 3;
    const int vb = (p2i & 7) * 16;

    for (int i = t; i < 16*68; i += 256) sSb[i] = 0u;
    __syncthreads();

    float S[16];
    #pragma unroll
    for (int i = 0; i < 16; i++) S[i] = 0.f;
    float C[8];
    uint4 AF[4];
    uint4 A[8];
    uint4 K[8];
    uint32_t ur[4];

    // gate chunks 0..3 before initial prefetch
    for (int c = 0; c < 4; c++) wait_flag(bh*NCH + c);

    const uint32_t* aL1 = isv ? g_wfh : g_qefh;
    {
        const uint4* Ab = (const uint4*)(aL1 + (size_t)(bh*NCH)*4096) + (mr*8)*32 + l;
        #pragma unroll
        for (int j = 0; j < 8; j++) A[j] = Ab[j*32];
        if (isv) {
            const uint4* Kb = (const uint4*)(g_krfh + (size_t)(bh*NCH)*4096) + l;
            #pragma unroll
            for (int mt = 0; mt < 2; mt++)
                #pragma unroll
                for (int kc = 0; kc < 4; kc++)
                    K[mt*4+kc] = Kb[((2*mr+mt)*4 + kc)*32];
            const uint32_t* up = (const uint32_t*)(g_uh + (size_t)(bh*SEQ + 16*mr + g)*DVD + vb);
            ur[0] = up[tig]; ur[1] = up[4+tig];
            ur[2] = up[512+tig]; ur[3] = up[512+4+tig];
        }
    }

    for (int n = 0; n < NCH; n++) {
        // gate: every 4 steps, ensure chunks n+1..n+4 are published
        if ((n & 3) == 0) {
            int hi = n + 4; if (hi > NCH-1) hi = NCH-1;
            for (int c = n + 1; c <= hi; c++) wait_flag(bh*NCH + c);
        }

        const int cid = bh*NCH + n;
        const size_t rb = (size_t)bh*SEQ + (size_t)n*BT;
        const int cur = n & 1;
        uint32_t* sSr  = sSb  + cur*(16*68);
        uint32_t* sSw  = sSb  + (cur^1)*(16*68);
        uint32_t* svnw = svnb + cur*(16*36);
        uint32_t* svno = svnb + (cur^1)*(16*36);

        if (isv) {
            float2 f0 = __half22float2(*(__half2*)&ur[0]);
            float2 f1 = __half22float2(*(__half2*)&ur[1]);
            float2 f2 = __half22float2(*(__half2*)&ur[2]);
            float2 f3 = __half22float2(*(__half2*)&ur[3]);
            float a0=f0.x,a1=f0.y,a4=f1.x,a5=f1.y,a2=f2.x,a3=f2.y,a6=f3.x,a7=f3.y;
            #pragma unroll
            for (int kc = 0; kc < 8; kc++) {
                uint32_t b00 = sSr[(g  )*68 + 8*kc     + tig];
                uint32_t b01 = sSr[(g  )*68 + 8*kc + 4 + tig];
                uint32_t b10 = sSr[(8+g)*68 + 8*kc     + tig];
                uint32_t b11 = sSr[(8+g)*68 + 8*kc + 4 + tig];
                mma16(a0,a1,a2,a3, A[kc].x,A[kc].y,A[kc].z,A[kc].w, b00,b01);
                mma16(a4,a5,a6,a7, A[kc].x,A[kc].y,A[kc].z,A[kc].w, b10,b11);
            }
            if (n + 1 < NCH) {
                const uint4* Ab = (const uint4*)(g_wfh + (size_t)(cid+1)*4096) + (mr*8)*32 + l;
                #pragma unroll
                for (int j = 0; j < 8; j++) A[j] = Ab[j*32];
            }
            {
                __half* svnh = (__half*)svnw;
                int p0 = (16*mr + g) >> 1, hb = g & 1;
                svnh[((2*tig  )*36 + p0  )*2 + hb] = __float2half_rn(a0);
                svnh[((2*tig+1)*36 + p0  )*2 + hb] = __float2half_rn(a1);
                svnh[((2*tig  )*36 + p0+4)*2 + hb] = __float2half_rn(a2);
                svnh[((2*tig+1)*36 + p0+4)*2 + hb] = __float2half_rn(a3);
                svnh[((8+2*tig  )*36 + p0  )*2 + hb] = __float2half_rn(a4);
                svnh[((8+2*tig+1)*36 + p0  )*2 + hb] = __float2half_rn(a5);
                svnh[((8+2*tig  )*36 + p0+4)*2 + hb] = __float2half_rn(a6);
                svnh[((8+2*tig+1)*36 + p0+4)*2 + hb] = __float2half_rn(a7);
            }
            asm volatile("bar.sync 1, 128;" ::: "memory");

            {
                const float egl = g_egl[cid];
                #pragma unroll
                for (int i = 0; i < 16; i++) S[i] *= egl;
                #pragma unroll
                for (int kc = 0; kc < 4; kc++) {
                    uint32_t b00 = svnw[(g  )*36 + 8*kc     + tig];
                    uint32_t b01 = svnw[(g  )*36 + 8*kc + 4 + tig];
                    uint32_t b10 = svnw[(8+g)*36 + 8*kc     + tig];
                    uint32_t b11 = svnw[(8+g)*36 + 8*kc + 4 + tig];
                    mma16(S[0], S[1], S[2], S[3],  K[kc  ].x,K[kc  ].y,K[kc  ].z,K[kc  ].w, b00,b01);
                    mma16(S[4], S[5], S[6], S[7],  K[kc  ].x,K[kc  ].y,K[kc  ].z,K[kc  ].w, b10,b11);
                    mma16(S[8], S[9], S[10],S[11], K[4+kc].x,K[4+kc].y,K[4+kc].z,K[4+kc].w, b00,b01);
                    mma16(S[12],S[13],S[14],S[15], K[4+kc].x,K[4+kc].y,K[4+kc].z,K[4+kc].w, b10,b11);
                }
                __half* sSh = (__half*)sSw;
                #pragma unroll
                for (int mt = 0; mt < 2; mt++) {
                    int r = 32*mr + 16*mt + g;
                    int p = r >> 1, hb2 = r & 1;
                    #pragma unroll
                    for (int nh = 0; nh < 2; nh++) {
                        int c0 = nh*8 + 2*tig;
                        const float* sp = S + mt*8 + nh*4;
                        sSh[((c0  )*68 + p  )*2 + hb2] = __float2half_rn(sp[0]);
                        sSh[((c0+1)*68 + p  )*2 + hb2] = __float2half_rn(sp[1]);
                        sSh[((c0  )*68 + p+4)*2 + hb2] = __float2half_rn(sp[2]);
                        sSh[((c0+1)*68 + p+4)*2 + hb2] = __float2half_rn(sp[3]);
                    }
                }
            }
            if (n + 1 < NCH) {
                const uint4* Kb = (const uint4*)(g_krfh + (size_t)(cid+1)*4096) + l;
                #pragma unroll
                for (int mt = 0; mt < 2; mt++)
                    #pragma unroll
                    for (int kc = 0; kc < 4; kc++)
                        K[mt*4+kc] = Kb[((2*mr+mt)*4 + kc)*32];
                const uint32_t* up = (const uint32_t*)(g_uh + (rb + BT + 16*mr + g)*DVD + vb);
                ur[0] = up[tig]; ur[1] = up[4+tig];
                ur[2] = up[512+tig]; ur[3] = up[512+4+tig];
            }
        } else {
            if (n > 0) {
                #pragma unroll
                for (int kc = 0; kc < 4; kc++) {
                    uint32_t b00 = svno[(g  )*36 + 8*kc     + tig];
                    uint32_t b01 = svno[(g  )*36 + 8*kc + 4 + tig];
                    uint32_t b10 = svno[(8+g)*36 + 8*kc     + tig];
                    uint32_t b11 = svno[(8+g)*36 + 8*kc + 4 + tig];
                    mma16(C[0],C[1],C[2],C[3], AF[kc].x,AF[kc].y,AF[kc].z,AF[kc].w, b00,b01);
                    mma16(C[4],C[5],C[6],C[7], AF[kc].x,AF[kc].y,AF[kc].z,AF[kc].w, b10,b11);
                }
                float* d0 = out + (rb - BT + 16*mr + g)*DVD + vb;
                float* d1 = d0 + 8*DVD;
                *(float2*)(d0 +     2*tig) = make_float2(C[0], C[1]);
                *(float2*)(d1 +     2*tig) = make_float2(C[2], C[3]);
                *(float2*)(d0 + 8 + 2*tig) = make_float2(C[4], C[5]);
                *(float2*)(d1 + 8 + 2*tig) = make_float2(C[6], C[7]);
            }
            {
                const uint4* Fb = (const uint4*)(g_Afh + (size_t)cid*2048) + (mr*4)*32 + l;
                #pragma unroll
                for (int kc = 0; kc < 4; kc++) AF[kc] = Fb[kc*32];
            }
            #pragma unroll
            for (int i = 0; i < 8; i++) C[i] = 0.f;
            #pragma unroll
            for (int kc = 0; kc < 8; kc++) {
                uint32_t b00 = sSr[(g  )*68 + 8*kc     + tig];
                uint32_t b01 = sSr[(g  )*68 + 8*kc + 4 + tig];
                uint32_t b10 = sSr[(8+g)*68 + 8*kc     + tig];
                uint32_t b11 = sSr[(8+g)*68 + 8*kc + 4 + tig];
                mma16(C[0],C[1],C[2],C[3], A[kc].x,A[kc].y,A[kc].z,A[kc].w, b00,b01);
                mma16(C[4],C[5],C[6],C[7], A[kc].x,A[kc].y,A[kc].z,A[kc].w, b10,b11);
            }
            if (n + 1 < NCH) {
                const uint4* Ab = (const uint4*)(g_qefh + (size_t)(cid+1)*4096) + (mr*8)*32 + l;
                #pragma unroll
                for (int j = 0; j < 8; j++) A[j] = Ab[j*32];
            }
        }
        __syncthreads();
    }

    if (!isv) {
        uint32_t* svno = svnb + ((NCH-1) & 1)*(16*36);
        #pragma unroll
        for (int kc = 0; kc < 4; kc++) {
            uint32_t b00 = svno[(g  )*36 + 8*kc     + tig];
            uint32_t b01 = svno[(g  )*36 + 8*kc + 4 + tig];
            uint32_t b10 = svno[(8+g)*36 + 8*kc     + tig];
            uint32_t b11 = svno[(8+g)*36 + 8*kc + 4 + tig];
            mma16(C[0],C[1],C[2],C[3], AF[kc].x,AF[kc].y,AF[kc].z,AF[kc].w, b00,b01);
            mma16(C[4],C[5],C[6],C[7], AF[kc].x,AF[kc].y,AF[kc].z,AF[kc].w, b10,b11);
        }
        float* d0 = out + ((size_t)bh*SEQ + (size_t)(NCH-1)*BT + 16*mr + g)*DVD + vb;
        float* d1 = d0 + 8*DVD;
        *(float2*)(d0 +     2*tig) = make_float2(C[0], C[1]);
        *(float2*)(d1 +     2*tig) = make_float2(C[2], C[3]);
        *(float2*)(d0 + 8 + 2*tig) = make_float2(C[4], C[5]);
        *(float2*)(d1 + 8 + 2*tig) = make_float2(C[6], C[7]);
    }

    if (write_sf && isv) {
        float* base = out + OSZ + (size_t)bh*DKD*DVD + vb;
        #pragma unroll
        for (int mt = 0; mt < 2; mt++) {
            int r = 32*mr + 16*mt + g;
            #pragma unroll
            for (int nh = 0; nh < 2; nh++) {
                const float* sp = S + mt*8 + nh*4;
                *(float2*)(base + (size_t)(r    )*DVD + nh*8 + 2*tig) = make_float2(sp[0], sp[1]);
                *(float2*)(base + (size_t)(r + 8)*DVD + nh*8 + 2*tig) = make_float2(sp[2], sp[3]);
            }
        }
    }
}

// ---------------------------------------------------------------------------
// Fused kernel: blocks 0..127 = p2 consumers; 128..2175 = p1 producers in
// n-major order (all bh of chunk n before chunk n+1).
// ---------------------------------------------------------------------------
__global__ void __launch_bounds__(256, 2) fused_kernel(
    const float* __restrict__ q, const float* __restrict__ k,
    const float* __restrict__ v, const float* __restrict__ gg,
    const float* __restrict__ beta, float* __restrict__ out, int write_sf)
{
    extern __shared__ float sm[];
    if (blockIdx.x < 128) {
        p2_body(sm, blockIdx.x, out, write_sf);
    } else {
        int p1i = blockIdx.x - 128;
        int n   = p1i >> 4;          // chunk index (low first)
        int bh  = p1i & 15;
        int cid = bh*NCH + n;
        int rowbase = bh*SEQ + n*BT;
        p1_body(sm, cid, rowbase, q, k, v, gg, beta);
    }
}

// ---------------------------------------------------------------------------
extern "C" void kernel_launch(void* const* d_in, const int* in_sizes, int n_in,
                              void* d_out, int out_size)
{
    const float* q    = (const float*)d_in[0];
    const float* k    = (const float*)d_in[1];
    const float* v    = (const float*)d_in[2];
    const float* g    = (const float*)d_in[3];
    const float* beta = (const float*)d_in[4];
    float* out = (float*)d_out;

    cudaFuncSetAttribute(fused_kernel, cudaFuncAttributeMaxDynamicSharedMemorySize, FUSED_SMEM);

    zero_flags_kernel<<<8, 256>>>();

    int wsf = (out_size > OSZ) ? 1 : 0;
    fused_kernel<<<128 + NCHUNKS, 256, FUSED_SMEM>>>(q, k, v, g, beta, out, wsf);
}